// round 11
// baseline (speedup 1.0000x reference)
#include <cuda_runtime.h>
#include <cuda_bf16.h>
#include <math.h>
#include <stdint.h>

// ---------------- problem constants ----------------
#define BB 8
#define NN 16384
#define SS 4096
#define KK 32
#define CC 64
#define NCOL (BB*SS*KK)          // 1048576 columns
#define NGRP (NCOL/32)           // 32768 (b,s) groups
#define BN_EPS 1e-5f
#define INF_F 3.0e38f

// ---------------- scratch layout (floats) ----------------
#define OFF_Y0T     ((size_t)0)           // (B,N,64)
#define OFF_XYZT    ((size_t)8388608)     // (B,N,4)
#define OFF_NXYZT   ((size_t)8912896)     // (B,S,4)
#define OFF_Z       ((size_t)9043968)     // fragment-blob Z: 8192 blocks x 8192 f32
#define OFF_MM      ((size_t)76152832)    // 128 x NGRP float2
#define OFF_WD      ((size_t)84541440)    // w0 dup image + HMMA A-fragment images
#define SCR_TOTAL   ((size_t)84590592)

__device__ float g_scr[SCR_TOTAL];
__device__ int   g_idx[SS*KK];
__device__ float g_ps[3][32][128];
__device__ float g_pq[3][32][128];
__device__ float g_bna[3*128];
__device__ float g_bnc[3*128];

// single shared symbol; kernels cast locally
extern __shared__ char s_raw[];

static __device__ __forceinline__ int clampN(int n) {
    return n < 0 ? 0 : (n >= NN ? NN-1 : n);
}

typedef unsigned long long ull;
#define FX2(acc, w, x) \
    asm("fma.rn.f32x2 %0, %1, %2, %0;" : "+l"(acc) : "l"(w), "l"(x))
#define UNPK(lo, hi, p) \
    asm("mov.b64 {%0, %1}, %2;" : "=f"(lo), "=f"(hi) : "l"(p))

__device__ __forceinline__ uint32_t pack2bf16(float a, float b) {
    __nv_bfloat162 h = __floats2bfloat162_rn(a, b);
    return *(uint32_t*)&h;
}

// HMMA m16n8k16 bf16 -> f32
#define MMA(acc, a, b0, b1) \
    asm("mma.sync.aligned.m16n8k16.row.col.f32.bf16.bf16.f32 " \
        "{%0,%1,%2,%3}, {%4,%5,%6,%7}, {%8,%9}, {%0,%1,%2,%3};" \
        : "+f"((acc)[0]), "+f"((acc)[1]), "+f"((acc)[2]), "+f"((acc)[3]) \
        : "r"((a).x), "r"((a).y), "r"((a).z), "r"((a).w), "r"(b0), "r"(b1))

// ---------------- prep: new_xyz + xyz transpose + clear stats (fused) ----------
__global__ void __launch_bounds__(256) k_prep0(const float* __restrict__ xyz,
                                               const int* __restrict__ perm,
                                               float* __restrict__ out) {
    int t = blockIdx.x*256 + threadIdx.x;
    if (t < 3*32*128) { ((float*)g_ps)[t] = 0.f; ((float*)g_pq)[t] = 0.f; }
    if (t < BB*NN) {        // xyz transpose (B,3,N) -> (B,N,4)
        int b = t >> 14, n = t & (NN-1);
        #pragma unroll
        for (int c = 0; c < 3; ++c)
            g_scr[OFF_XYZT + ((size_t)(b*NN + n))*4 + c] = xyz[((size_t)b*3 + c)*NN + n];
        g_scr[OFF_XYZT + ((size_t)(b*NN + n))*4 + 3] = 0.f;
    }
    if (t < BB*SS) {        // new_xyz output + query coords
        int b = t / SS, s = t % SS;
        int n = clampN(perm[s]);
        #pragma unroll
        for (int c = 0; c < 3; ++c) {
            float v = xyz[((size_t)b*3 + c)*NN + n];
            out[((size_t)b*3 + c)*SS + s] = v;
            g_scr[OFF_NXYZT + ((size_t)(b*SS + s))*4 + c] = v;
        }
        g_scr[OFF_NXYZT + ((size_t)(b*SS + s))*4 + 3] = 0.f;
    }
}

// ---------------- prep: w0 dup image + HMMA A-fragment images (hi/lo) ----------
// Frag layout: img[pass][w][ks][lane][reg] u32
// reg0:(g, tig*2) reg1:(g+8, tig*2) reg2:(g, tig*2+8) reg3:(g+8, tig*2+8)
__global__ void __launch_bounds__(256) k_prepw(const float* __restrict__ w0,
                                               const float* __restrict__ w1,
                                               const float* __restrict__ w2) {
    int t = blockIdx.x*256 + threadIdx.x;
    if (t >= 16384) return;
    if (t < 4096) {                      // gemm0 dup-pair image (w0[:, :64])
        int m = t >> 6, kk = t & 63;
        float v = w0[m*67 + kk];
        float* dst = g_scr + OFF_WD + (size_t)kk*128 + 2*m;
        dst[0] = v; dst[1] = v;
        return;
    }
    const float* W; uint32_t* base; int NW, u;
    uint32_t* wf = (uint32_t*)(g_scr + OFF_WD);
    if (t < 8192) { W = w1; NW = 4; u = t - 4096; base = wf + 16384; }
    else          { W = w2; NW = 8; u = t - 8192; base = wf + 20480; }
    int pass = u / (NW*512);
    int rest = u - pass*NW*512;
    int w = rest >> 9, ks = (rest >> 7) & 3, l = (rest >> 2) & 31, reg = rest & 3;
    int g = l >> 2, tig = l & 3;
    int m = w*16 + g + 8*(reg & 1);
    int k = ks*16 + tig*2 + 8*(reg >> 1);
    float v0 = W[m*64 + k], v1 = W[m*64 + k + 1];
    __nv_bfloat16 h0 = __float2bfloat16_rn(v0), h1 = __float2bfloat16_rn(v1);
    float f0 = __bfloat162float(h0), f1 = __bfloat162float(h1);
    base[u] = (pass == 0) ? pack2bf16(f0, f1) : pack2bf16(v0 - f0, v1 - f1);
}

// ---------------- KNN: TWO warps per query (split support), merged at end ------
// Warp pair (h=0,1) each scans 8192 candidates with the distributed register
// top-32 + tracked (worst, wlane). h=1 dumps its 32 entries to smem; h=0
// re-inserts them serially (broadcast reads) and writes the final 32 indices.
__global__ void __launch_bounds__(256) k_knn() {
    __shared__ float4 s_tile[2048];
    __shared__ float  s_md[4][32];
    __shared__ int    s_mi[4][32];
    int tid = threadIdx.x;
    int w = tid >> 5, lane = tid & 31;
    int ql = w >> 1, h = w & 1;
    int q = blockIdx.x*4 + ql;
    const float4* xt = (const float4*)(g_scr + OFF_XYZT);
    float4 qp = ((const float4*)(g_scr + OFF_NXYZT))[q];
    float qq = qp.x*qp.x + qp.y*qp.y + qp.z*qp.z;
    float myd = INF_F; int myi = 0;
    float worst = INF_F; int wlane = 0;
    for (int tile = 0; tile < 8; ++tile) {
        __syncthreads();
        for (int i = tid; i < 2048; i += 256) {
            float4 p = xt[tile*2048 + i];
            p.w = p.x*p.x + p.y*p.y + p.z*p.z;
            s_tile[i] = p;
        }
        __syncthreads();
        #pragma unroll 4
        for (int j = 0; j < 32; ++j) {
            int ii = h*1024 + j*32 + lane;
            float4 p = s_tile[ii];
            float d = qq - 2.f*(qp.x*p.x + qp.y*p.y + qp.z*p.z) + p.w;
            int idx = tile*2048 + ii;
            unsigned hits = __ballot_sync(0xffffffffu, d < worst);
            while (hits) {
                int src = __ffs(hits) - 1;
                hits &= hits - 1;
                float dc = __shfl_sync(0xffffffffu, d, src);
                int   ic = __shfl_sync(0xffffffffu, idx, src);
                if (dc < worst) {
                    if (lane == wlane) { myd = dc; myi = ic; }
                    float v = myd; int pos = lane;
                    #pragma unroll
                    for (int off = 16; off; off >>= 1) {
                        float ov = __shfl_xor_sync(0xffffffffu, v, off);
                        int   op = __shfl_xor_sync(0xffffffffu, pos, off);
                        if (ov > v || (ov == v && op < pos)) { v = ov; pos = op; }
                    }
                    worst = v; wlane = pos;
                }
            }
        }
    }
    __syncthreads();
    if (h == 1) { s_md[ql][lane] = myd; s_mi[ql][lane] = myi; }
    __syncthreads();
    if (h == 0) {
        #pragma unroll 4
        for (int r = 0; r < 32; ++r) {
            float dc = s_md[ql][r];
            if (dc < worst) {
                int ic = s_mi[ql][r];
                if (lane == wlane) { myd = dc; myi = ic; }
                float v = myd; int pos = lane;
                #pragma unroll
                for (int off = 16; off; off >>= 1) {
                    float ov = __shfl_xor_sync(0xffffffffu, v, off);
                    int   op = __shfl_xor_sync(0xffffffffu, pos, off);
                    if (ov > v || (ov == v && op < pos)) { v = ov; pos = op; }
                }
                worst = v; wlane = pos;
            }
        }
        g_idx[q*32 + lane] = myi;
    }
}

// ---------------- k_gemm0: FFMA2, Y0T[b][n][64] per distinct point ----------
#define XS 132
__global__ void __launch_bounds__(128) k_gemm0(const float* __restrict__ feats) {
    float* smem = (float*)s_raw;
    float* shx = smem + 512;
    float* shw = smem + 512 + 64*XS;
    int tid = threadIdx.x;
    int tx = tid & 15, ty = tid >> 4;
    int b  = blockIdx.x >> 7;
    int n0 = (blockIdx.x & 127) * 128;
    {
        const float4* src = (const float4*)(g_scr + OFF_WD);
        float4* dst = (float4*)shw;
        #pragma unroll
        for (int i = tid; i < 2048; i += 128) dst[i] = src[i];
    }
    {
        const float* fb = feats + (size_t)b*CC*NN + n0;
        #pragma unroll
        for (int i = tid; i < 2048; i += 128) {
            int kk = i >> 5, c4 = i & 31;
            *(float4*)(shx + kk*XS + c4*4) = *(const float4*)(fb + (size_t)kk*NN + c4*4);
        }
    }
    __syncthreads();
    ull acc[8][4];
    #pragma unroll
    for (int r = 0; r < 8; ++r)
        #pragma unroll
        for (int p = 0; p < 4; ++p) acc[r][p] = 0ull;
    #pragma unroll 4
    for (int kk = 0; kk < 64; ++kk) {
        const float* xrow = shx + kk*XS + 2*tx;
        ull x0 = *(const ull*)(xrow);
        ull x1 = *(const ull*)(xrow + 32);
        ull x2 = *(const ull*)(xrow + 64);
        ull x3 = *(const ull*)(xrow + 96);
        const ulonglong2* wrow = (const ulonglong2*)(shw + kk*128 + ty*16);
        #pragma unroll
        for (int j = 0; j < 4; ++j) {
            ulonglong2 wp = wrow[j];
            FX2(acc[2*j  ][0], wp.x, x0); FX2(acc[2*j  ][1], wp.x, x1);
            FX2(acc[2*j  ][2], wp.x, x2); FX2(acc[2*j  ][3], wp.x, x3);
            FX2(acc[2*j+1][0], wp.y, x0); FX2(acc[2*j+1][1], wp.y, x1);
            FX2(acc[2*j+1][2], wp.y, x2); FX2(acc[2*j+1][3], wp.y, x3);
        }
    }
    float v[4][2][8];
    #pragma unroll
    for (int r = 0; r < 8; ++r)
        #pragma unroll
        for (int p = 0; p < 4; ++p) {
            float lo, hi; UNPK(lo, hi, acc[r][p]);
            v[p][0][r] = lo; v[p][1][r] = hi;
        }
    #pragma unroll
    for (int p = 0; p < 4; ++p)
        #pragma unroll
        for (int e = 0; e < 2; ++e) {
            int n_g = n0 + 32*p + 2*tx + e;
            float* dst = g_scr + OFF_Y0T + ((size_t)(b*NN + n_g))*64 + ty*8;
            *(float4*)dst       = make_float4(v[p][e][0], v[p][e][1], v[p][e][2], v[p][e][3]);
            *(float4*)(dst + 4) = make_float4(v[p][e][4], v[p][e][5], v[p][e][6], v[p][e][7]);
        }
}

// ---------------- k_stats1: BN0 stats over virtual Z1 ----------------
__global__ void __launch_bounds__(256) k_stats1(const float* __restrict__ w0raw) {
    int warp = blockIdx.x*8 + (threadIdx.x >> 5);
    int lane = threadIdx.x & 31;
    int m0 = 2*lane;
    float wa0 = w0raw[m0*67 + 64],     wb0 = w0raw[m0*67 + 65],     wc0 = w0raw[m0*67 + 66];
    float wa1 = w0raw[(m0+1)*67 + 64], wb1 = w0raw[(m0+1)*67 + 65], wc1 = w0raw[(m0+1)*67 + 66];
    const float4* xt = (const float4*)(g_scr + OFF_XYZT);
    const float4* nx = (const float4*)(g_scr + OFF_NXYZT);
    float s0 = 0.f, q0 = 0.f, s1 = 0.f, q1 = 0.f;
    int base = warp*128;
    float4 qc = make_float4(0,0,0,0);
    int b = 0, s = 0;
    for (int j = 0; j < 128; ++j) {
        int col = base + j;
        int G = col >> 5, k = col & 31;
        if ((j & 31) == 0) { s = G & (SS-1); b = G >> 12; qc = nx[(size_t)b*SS + s]; }
        int n = g_idx[s*32 + k];
        float4 p = xt[(size_t)b*NN + n];
        float rx = p.x - qc.x, ry = p.y - qc.y, rz = p.z - qc.z;
        float2 y = *(const float2*)(g_scr + OFF_Y0T + ((size_t)(b*NN + n))*64 + m0);
        float z0 = fmaf(wa0, rx, fmaf(wb0, ry, fmaf(wc0, rz, y.x)));
        float z1 = fmaf(wa1, rx, fmaf(wb1, ry, fmaf(wc1, rz, y.y)));
        s0 += z0; q0 = fmaf(z0, z0, q0);
        s1 += z1; q1 = fmaf(z1, z1, q1);
    }
    int bkt = warp & 31;
    atomicAdd(&g_ps[0][bkt][m0],   s0); atomicAdd(&g_pq[0][bkt][m0],   q0);
    atomicAdd(&g_ps[0][bkt][m0+1], s1); atomicAdd(&g_pq[0][bkt][m0+1], q1);
}

// ---------------- k_mma1: HMMA, Z(blob) = W1 @ relu(bn0(gather+rank3)) ----------
// smem: par f32[320]@0 | A u32[4096]@1536 | BH u32[4608]@17920 | BL@36352 (54784B)
__global__ void __launch_bounds__(128) k_mma1(const float* __restrict__ w0raw) {
    char* smem = s_raw;
    float*    sm_par = (float*)smem;
    uint32_t* Asm = (uint32_t*)(smem + 1536);
    uint32_t* BH  = (uint32_t*)(smem + 17920);
    uint32_t* BL  = (uint32_t*)(smem + 36352);
    int tid = threadIdx.x, lane = tid & 31, w = tid >> 5;
    int g = lane >> 2, tig = lane & 3;

    {   // A-fragment image (hi+lo) -> smem
        const uint4* src = (const uint4*)((const uint32_t*)(g_scr + OFF_WD) + 16384);
        uint4* dst = (uint4*)Asm;
        #pragma unroll
        for (int i = tid; i < 1024; i += 128) dst[i] = src[i];
    }
    if (tid < 64) {
        sm_par[tid]       = w0raw[tid*67 + 64];
        sm_par[64 + tid]  = w0raw[tid*67 + 65];
        sm_par[128 + tid] = w0raw[tid*67 + 66];
        sm_par[192 + tid] = g_bna[tid];
        sm_par[256 + tid] = g_bnc[tid];
    }
    __syncthreads();

    {   // B build: one thread per column; BN0+ReLU+hi/lo split, frag layout
        int col = blockIdx.x*128 + tid;
        int G = col >> 5, k = col & 31;
        int s = G & (SS-1), b = G >> 12;
        int n = g_idx[s*32 + k];
        const float4* fr = (const float4*)(g_scr + OFF_Y0T + ((size_t)(b*NN + n))*64);
        float4 p  = ((const float4*)(g_scr + OFF_XYZT))[(size_t)b*NN + n];
        float4 qc = ((const float4*)(g_scr + OFF_NXYZT))[(size_t)b*SS + s];
        float rx = p.x - qc.x, ry = p.y - qc.y, rz = p.z - qc.z;
        #pragma unroll
        for (int i = 0; i < 16; ++i) {
            float4 y = fr[i];
            float yy[4] = {y.x, y.y, y.z, y.w};
            #pragma unroll
            for (int h = 0; h < 2; ++h) {
                int m0 = 4*i + 2*h;
                float z0 = fmaf(sm_par[m0], rx, fmaf(sm_par[64+m0], ry, fmaf(sm_par[128+m0], rz, yy[2*h])));
                z0 = fmaxf(fmaf(sm_par[192+m0], z0, sm_par[256+m0]), 0.f);
                int m1 = m0 + 1;
                float z1 = fmaf(sm_par[m1], rx, fmaf(sm_par[64+m1], ry, fmaf(sm_par[128+m1], rz, yy[2*h+1])));
                z1 = fmaxf(fmaf(sm_par[192+m1], z1, sm_par[256+m1]), 0.f);
                __nv_bfloat16 h0 = __float2bfloat16_rn(z0), h1 = __float2bfloat16_rn(z1);
                float f0 = __bfloat162float(h0), f1 = __bfloat162float(h1);
                int kp = 2*i + h;
                BH[tid*36 + kp] = pack2bf16(f0, f1);
                BL[tid*36 + kp] = pack2bf16(z0 - f0, z1 - f1);
            }
        }
    }
    __syncthreads();

    float acc[16][4];
    #pragma unroll
    for (int tt = 0; tt < 16; ++tt)
        #pragma unroll
        for (int c = 0; c < 4; ++c) acc[tt][c] = 0.f;

    #pragma unroll
    for (int ks = 0; ks < 4; ++ks) {
        uint4 ah = *(const uint4*)(Asm + w*512 + ks*128 + lane*4);
        uint4 al = *(const uint4*)(Asm + 2048 + w*512 + ks*128 + lane*4);
        #pragma unroll
        for (int tt = 0; tt < 16; ++tt) {
            int ba = (tt*8 + g)*36 + ks*8 + tig;
            uint32_t b0h = BH[ba], b1h = BH[ba + 4];
            uint32_t b0l = BL[ba], b1l = BL[ba + 4];
            MMA(acc[tt], ah, b0h, b1h);
            MMA(acc[tt], al, b0h, b1h);
            MMA(acc[tt], ah, b0l, b1l);
        }
    }

    // epilogue: blob store + stats
    float4* zb = (float4*)(g_scr + OFF_Z) + (size_t)blockIdx.x*2048;
    float sg = 0.f, qg = 0.f, s8 = 0.f, q8 = 0.f;
    #pragma unroll
    for (int tt = 0; tt < 16; ++tt) {
        zb[tt*128 + w*32 + lane] = make_float4(acc[tt][0], acc[tt][1], acc[tt][2], acc[tt][3]);
        sg += acc[tt][0] + acc[tt][1];
        qg = fmaf(acc[tt][0], acc[tt][0], fmaf(acc[tt][1], acc[tt][1], qg));
        s8 += acc[tt][2] + acc[tt][3];
        q8 = fmaf(acc[tt][2], acc[tt][2], fmaf(acc[tt][3], acc[tt][3], q8));
    }
    #pragma unroll
    for (int o = 2; o; o >>= 1) {
        sg += __shfl_down_sync(0xffffffffu, sg, o, 4);
        qg += __shfl_down_sync(0xffffffffu, qg, o, 4);
        s8 += __shfl_down_sync(0xffffffffu, s8, o, 4);
        q8 += __shfl_down_sync(0xffffffffu, q8, o, 4);
    }
    if (tig == 0) {
        int bkt = blockIdx.x & 31;
        int m = w*16 + g;
        atomicAdd(&g_ps[1][bkt][m],     sg); atomicAdd(&g_pq[1][bkt][m],     qg);
        atomicAdd(&g_ps[1][bkt][m + 8], s8); atomicAdd(&g_pq[1][bkt][m + 8], q8);
    }
}

// ---------------- k_mma2: HMMA, maxpool(relu(bn2(W2 @ relu(bn1(Zblob))))) ------
// smem: bna[64]@0 bnc[64]@256 | A u32[8192]@512 | BH@33280 | BL@51712 (70144B)
__global__ void __launch_bounds__(256) k_mma2() {
    char* smem = s_raw;
    float*    bna = (float*)smem;
    float*    bnc = (float*)(smem + 256);
    uint32_t* Asm = (uint32_t*)(smem + 512);
    uint32_t* BH  = (uint32_t*)(smem + 33280);
    uint32_t* BL  = (uint32_t*)(smem + 51712);
    int tid = threadIdx.x, lane = tid & 31, w = tid >> 5;
    int g = lane >> 2, tig = lane & 3;

    {
        const uint4* src = (const uint4*)((const uint32_t*)(g_scr + OFF_WD) + 20480);
        uint4* dst = (uint4*)Asm;
        #pragma unroll
        for (int i = tid; i < 2048; i += 256) dst[i] = src[i];
    }
    if (tid < 64) { bna[tid] = g_bna[128 + tid]; bnc[tid] = g_bnc[128 + tid]; }
    __syncthreads();

    {   // prologue: decode blob -> BN1/ReLU -> hi/lo B fragments
        const float* zb = g_scr + OFF_Z + (size_t)blockIdx.x*8192;
        #pragma unroll
        for (int j = 0; j < 16; ++j) {
            int p = j*256 + tid;
            int ptig = p & 3, c = (p >> 2) & 3, gh = (p >> 4) & 3;
            int w1 = (p >> 6) & 3, tt = p >> 8;
            int i0 = tt*512 + w1*128 + gh*32 + ptig*4 + c;
            float z0 = zb[i0], z1 = zb[i0 + 16];
            int kch = w1*16 + 2*gh + 8*(c >> 1);
            z0 = fmaxf(fmaf(bna[kch],     z0, bnc[kch]),     0.f);
            z1 = fmaxf(fmaf(bna[kch + 1], z1, bnc[kch + 1]), 0.f);
            __nv_bfloat16 h0 = __float2bfloat16_rn(z0), h1 = __float2bfloat16_rn(z1);
            float f0 = __bfloat162float(h0), f1 = __bfloat162float(h1);
            int col = tt*8 + ptig*2 + (c & 1);
            int kp  = w1*8 + gh + 4*(c >> 1);
            BH[col*36 + kp] = pack2bf16(f0, f1);
            BL[col*36 + kp] = pack2bf16(z0 - f0, z1 - f1);
        }
    }
    __syncthreads();

    float acc[16][4];
    #pragma unroll
    for (int tt = 0; tt < 16; ++tt)
        #pragma unroll
        for (int c = 0; c < 4; ++c) acc[tt][c] = 0.f;

    #pragma unroll
    for (int ks = 0; ks < 4; ++ks) {
        uint4 ah = *(const uint4*)(Asm + w*512 + ks*128 + lane*4);
        uint4 al = *(const uint4*)(Asm + 4096 + w*512 + ks*128 + lane*4);
        #pragma unroll
        for (int tt = 0; tt < 16; ++tt) {
            int ba = (tt*8 + g)*36 + ks*8 + tig;
            uint32_t b0h = BH[ba], b1h = BH[ba + 4];
            uint32_t b0l = BL[ba], b1l = BL[ba + 4];
            MMA(acc[tt], ah, b0h, b1h);
            MMA(acc[tt], al, b0h, b1h);
            MMA(acc[tt], ah, b0l, b1l);
        }
    }

    // epilogue: per-32-col max/min pools + stats
    float2* mm = (float2*)(g_scr + OFF_MM);
    float sg = 0.f, qg = 0.f, s8 = 0.f, q8 = 0.f;
    #pragma unroll
    for (int p = 0; p < 4; ++p) {
        float mxg = -INF_F, mng = INF_F, mx8 = -INF_F, mn8 = INF_F;
        #pragma unroll
        for (int t4 = 0; t4 < 4; ++t4) {
            int tt = p*4 + t4;
            mxg = fmaxf(mxg, fmaxf(acc[tt][0], acc[tt][1]));
            mng = fminf(mng, fminf(acc[tt][0], acc[tt][1]));
            mx8 = fmaxf(mx8, fmaxf(acc[tt][2], acc[tt][3]));
            mn8 = fminf(mn8, fminf(acc[tt][2], acc[tt][3]));
            sg += acc[tt][0] + acc[tt][1];
            qg = fmaf(acc[tt][0], acc[tt][0], fmaf(acc[tt][1], acc[tt][1], qg));
            s8 += acc[tt][2] + acc[tt][3];
            q8 = fmaf(acc[tt][2], acc[tt][2], fmaf(acc[tt][3], acc[tt][3], q8));
        }
        #pragma unroll
        for (int o = 2; o; o >>= 1) {
            mxg = fmaxf(mxg, __shfl_down_sync(0xffffffffu, mxg, o, 4));
            mng = fminf(mng, __shfl_down_sync(0xffffffffu, mng, o, 4));
            mx8 = fmaxf(mx8, __shfl_down_sync(0xffffffffu, mx8, o, 4));
            mn8 = fminf(mn8, __shfl_down_sync(0xffffffffu, mn8, o, 4));
        }
        if (tig == 0) {
            int m = w*16 + g;
            mm[(size_t)m*NGRP + blockIdx.x*4 + p]       = make_float2(mxg, mng);
            mm[(size_t)(m + 8)*NGRP + blockIdx.x*4 + p] = make_float2(mx8, mn8);
        }
    }
    #pragma unroll
    for (int o = 2; o; o >>= 1) {
        sg += __shfl_down_sync(0xffffffffu, sg, o, 4);
        qg += __shfl_down_sync(0xffffffffu, qg, o, 4);
        s8 += __shfl_down_sync(0xffffffffu, s8, o, 4);
        q8 += __shfl_down_sync(0xffffffffu, q8, o, 4);
    }
    if (tig == 0) {
        int bkt = blockIdx.x & 31;
        int m = w*16 + g;
        atomicAdd(&g_ps[2][bkt][m],     sg); atomicAdd(&g_pq[2][bkt][m],     qg);
        atomicAdd(&g_ps[2][bkt][m + 8], s8); atomicAdd(&g_pq[2][bkt][m + 8], q8);
    }
}

// ---------------- BN affine params ----------------
__global__ void k_bnparam(int slot, const float* __restrict__ g,
                          const float* __restrict__ b, int M) {
    int m = threadIdx.x;
    if (m >= M) return;
    float s = 0.f, q = 0.f;
    #pragma unroll
    for (int j = 0; j < 32; ++j) { s += g_ps[slot][j][m]; q += g_pq[slot][j][m]; }
    const float cnt = (float)NCOL;
    float mu  = s / cnt;
    float var = q / cnt - mu*mu;
    float a = g[m] * rsqrtf(var + BN_EPS);
    g_bna[slot*128 + m] = a;
    g_bnc[slot*128 + m] = b[m] - mu*a;
}

// ---------------- finalize ----------------
__global__ void __launch_bounds__(256) k_final(float* __restrict__ out) {
    int t = blockIdx.x*256 + threadIdx.x;
    if (t >= BB*128*SS) return;
    int s  = t & (SS-1);
    int bc = t >> 12;
    int c = bc & 127, b = bc >> 7;
    float a  = g_bna[2*128 + c];
    float cc = g_bnc[2*128 + c];
    const float2* mm = (const float2*)(g_scr + OFF_MM);
    float2 e = mm[(size_t)c*NGRP + b*SS + s];
    float z = (a >= 0.f) ? e.x : e.y;
    out[BB*3*SS + t] = fmaxf(fmaf(a, z, cc), 0.f);
}

// ---------------- launch ----------------
extern "C" void kernel_launch(void* const* d_in, const int* in_sizes, int n_in,
                              void* d_out, int out_size) {
    (void)in_sizes; (void)n_in; (void)out_size;
    const float* xyz   = (const float*)d_in[0];
    const float* feats = (const float*)d_in[1];
    const int*   perm  = (const int*)d_in[2];
    const float* w0 = (const float*)d_in[3];
    const float* g0 = (const float*)d_in[4];
    const float* b0 = (const float*)d_in[5];
    const float* w1 = (const float*)d_in[6];
    const float* g1 = (const float*)d_in[7];
    const float* b1 = (const float*)d_in[8];
    const float* w2 = (const float*)d_in[9];
    const float* g2 = (const float*)d_in[10];
    const float* b2 = (const float*)d_in[11];
    float* out = (float*)d_out;

    const int sm0  = (512 + 64*XS + 64*128) * 4;   // 68608 (gemm0)
    const int smm1 = 54784;
    const int smm2 = 70144;
    cudaFuncSetAttribute(k_gemm0, cudaFuncAttributeMaxDynamicSharedMemorySize, sm0);
    cudaFuncSetAttribute(k_mma1,  cudaFuncAttributeMaxDynamicSharedMemorySize, smm1);
    cudaFuncSetAttribute(k_mma2,  cudaFuncAttributeMaxDynamicSharedMemorySize, smm2);

    k_prep0 <<<(BB*NN)/256, 256>>>(xyz, perm, out);
    k_prepw <<<64, 256>>>(w0, w1, w2);
    k_knn   <<<SS/4, 256>>>();
    k_gemm0 <<<BB*NN/128, 128, sm0>>>(feats);
    k_stats1<<<NCOL/1024, 256>>>(w0);
    k_bnparam<<<1,128>>>(0, g0, b0, 64);
    k_mma1  <<<NCOL/128, 128, smm1>>>(w0);
    k_bnparam<<<1,128>>>(1, g1, b1, 64);
    k_mma2  <<<NCOL/128, 256, smm2>>>();
    k_bnparam<<<1,128>>>(2, g2, b2, 128);
    k_final<<<(BB*128*SS)/256, 256>>>(out);
}

// round 12
// speedup vs baseline: 1.0074x; 1.0074x over previous
#include <cuda_runtime.h>
#include <cuda_bf16.h>
#include <math.h>
#include <stdint.h>

// ---------------- problem constants ----------------
#define BB 8
#define NN 16384
#define SS 4096
#define KK 32
#define CC 64
#define NCOL (BB*SS*KK)          // 1048576 columns
#define NGRP (NCOL/32)           // 32768 (b,s) groups
#define BN_EPS 1e-5f
#define INF_F 3.0e38f

// ---------------- scratch layout (floats) ----------------
#define OFF_Y0T     ((size_t)0)           // (B,N,64)
#define OFF_XYZT    ((size_t)8388608)     // (B,N,4)
#define OFF_NXYZT   ((size_t)8912896)     // (B,S,4)
#define OFF_Z       ((size_t)9043968)     // fragment-blob Z: 8192 blocks x 8192 f32
#define OFF_MM      ((size_t)76152832)    // 128 x NGRP float2
#define OFF_WD      ((size_t)84541440)    // w0 dup image + HMMA A-fragment images
#define SCR_TOTAL   ((size_t)84590592)

__device__ float g_scr[SCR_TOTAL];
__device__ int   g_idx[SS*KK];
__device__ float g_ps[3][32][128];
__device__ float g_pq[3][32][128];
__device__ float g_bna[3*128];
__device__ float g_bnc[3*128];

// single shared symbol; kernels cast locally
extern __shared__ char s_raw[];

static __device__ __forceinline__ int clampN(int n) {
    return n < 0 ? 0 : (n >= NN ? NN-1 : n);
}

typedef unsigned long long ull;
#define FX2(acc, w, x) \
    asm("fma.rn.f32x2 %0, %1, %2, %0;" : "+l"(acc) : "l"(w), "l"(x))
#define UNPK(lo, hi, p) \
    asm("mov.b64 {%0, %1}, %2;" : "=f"(lo), "=f"(hi) : "l"(p))

__device__ __forceinline__ uint32_t pack2bf16(float a, float b) {
    __nv_bfloat162 h = __floats2bfloat162_rn(a, b);
    return *(uint32_t*)&h;
}

// HMMA m16n8k16 bf16 -> f32
#define MMA(acc, a, b0, b1) \
    asm("mma.sync.aligned.m16n8k16.row.col.f32.bf16.bf16.f32 " \
        "{%0,%1,%2,%3}, {%4,%5,%6,%7}, {%8,%9}, {%0,%1,%2,%3};" \
        : "+f"((acc)[0]), "+f"((acc)[1]), "+f"((acc)[2]), "+f"((acc)[3]) \
        : "r"((a).x), "r"((a).y), "r"((a).z), "r"((a).w), "r"(b0), "r"(b1))

// ---------------- prep: new_xyz + xyz transpose + clear stats (fused) ----------
__global__ void __launch_bounds__(256) k_prep0(const float* __restrict__ xyz,
                                               const int* __restrict__ perm,
                                               float* __restrict__ out) {
    int t = blockIdx.x*256 + threadIdx.x;
    if (t < 3*32*128) { ((float*)g_ps)[t] = 0.f; ((float*)g_pq)[t] = 0.f; }
    if (t < BB*NN) {        // xyz transpose (B,3,N) -> (B,N,4)
        int b = t >> 14, n = t & (NN-1);
        #pragma unroll
        for (int c = 0; c < 3; ++c)
            g_scr[OFF_XYZT + ((size_t)(b*NN + n))*4 + c] = xyz[((size_t)b*3 + c)*NN + n];
        g_scr[OFF_XYZT + ((size_t)(b*NN + n))*4 + 3] = 0.f;
    }
    if (t < BB*SS) {        // new_xyz output + query coords
        int b = t / SS, s = t % SS;
        int n = clampN(perm[s]);
        #pragma unroll
        for (int c = 0; c < 3; ++c) {
            float v = xyz[((size_t)b*3 + c)*NN + n];
            out[((size_t)b*3 + c)*SS + s] = v;
            g_scr[OFF_NXYZT + ((size_t)(b*SS + s))*4 + c] = v;
        }
        g_scr[OFF_NXYZT + ((size_t)(b*SS + s))*4 + 3] = 0.f;
    }
}

// ---------------- prep: w0 dup image + HMMA A-fragment images (hi/lo) ----------
__global__ void __launch_bounds__(256) k_prepw(const float* __restrict__ w0,
                                               const float* __restrict__ w1,
                                               const float* __restrict__ w2) {
    int t = blockIdx.x*256 + threadIdx.x;
    if (t >= 16384) return;
    if (t < 4096) {                      // gemm0 dup-pair image (w0[:, :64])
        int m = t >> 6, kk = t & 63;
        float v = w0[m*67 + kk];
        float* dst = g_scr + OFF_WD + (size_t)kk*128 + 2*m;
        dst[0] = v; dst[1] = v;
        return;
    }
    const float* W; uint32_t* base; int NW, u;
    uint32_t* wf = (uint32_t*)(g_scr + OFF_WD);
    if (t < 8192) { W = w1; NW = 4; u = t - 4096; base = wf + 16384; }
    else          { W = w2; NW = 8; u = t - 8192; base = wf + 20480; }
    int pass = u / (NW*512);
    int rest = u - pass*NW*512;
    int w = rest >> 9, ks = (rest >> 7) & 3, l = (rest >> 2) & 31, reg = rest & 3;
    int g = l >> 2, tig = l & 3;
    int m = w*16 + g + 8*(reg & 1);
    int k = ks*16 + tig*2 + 8*(reg >> 1);
    float v0 = W[m*64 + k], v1 = W[m*64 + k + 1];
    __nv_bfloat16 h0 = __float2bfloat16_rn(v0), h1 = __float2bfloat16_rn(v1);
    float f0 = __bfloat162float(h0), f1 = __bfloat162float(h1);
    base[u] = (pass == 0) ? pack2bf16(f0, f1) : pack2bf16(v0 - f0, v1 - f1);
}

// ---------------- KNN: 8 queries/block x 2 warps/query (512 threads) ----------
// Grid stays 512 (tile fill traffic unchanged vs round 10); per-warp serial
// scan halves. Warp pair (h=0,1) each scans half of every tile with the
// distributed register top-32 + tracked (worst, wlane); h=1 dumps its 32
// entries to smem, h=0 re-inserts them and writes the final indices.
__global__ void __launch_bounds__(512) k_knn() {
    __shared__ float4 s_tile[2048];
    __shared__ float  s_md[8][32];
    __shared__ int    s_mi[8][32];
    int tid = threadIdx.x;
    int w = tid >> 5, lane = tid & 31;
    int ql = w >> 1, h = w & 1;
    int q = blockIdx.x*8 + ql;
    const float4* xt = (const float4*)(g_scr + OFF_XYZT);
    float4 qp = ((const float4*)(g_scr + OFF_NXYZT))[q];
    float qq = qp.x*qp.x + qp.y*qp.y + qp.z*qp.z;
    float myd = INF_F; int myi = 0;
    float worst = INF_F; int wlane = 0;
    for (int tile = 0; tile < 8; ++tile) {
        __syncthreads();
        for (int i = tid; i < 2048; i += 512) {
            float4 p = xt[tile*2048 + i];
            p.w = p.x*p.x + p.y*p.y + p.z*p.z;
            s_tile[i] = p;
        }
        __syncthreads();
        #pragma unroll 4
        for (int j = 0; j < 32; ++j) {
            int ii = h*1024 + j*32 + lane;
            float4 p = s_tile[ii];
            float d = qq - 2.f*(qp.x*p.x + qp.y*p.y + qp.z*p.z) + p.w;
            int idx = tile*2048 + ii;
            unsigned hits = __ballot_sync(0xffffffffu, d < worst);
            while (hits) {
                int src = __ffs(hits) - 1;
                hits &= hits - 1;
                float dc = __shfl_sync(0xffffffffu, d, src);
                int   ic = __shfl_sync(0xffffffffu, idx, src);
                if (dc < worst) {
                    if (lane == wlane) { myd = dc; myi = ic; }
                    float v = myd; int pos = lane;
                    #pragma unroll
                    for (int off = 16; off; off >>= 1) {
                        float ov = __shfl_xor_sync(0xffffffffu, v, off);
                        int   op = __shfl_xor_sync(0xffffffffu, pos, off);
                        if (ov > v || (ov == v && op < pos)) { v = ov; pos = op; }
                    }
                    worst = v; wlane = pos;
                }
            }
        }
    }
    __syncthreads();
    if (h == 1) { s_md[ql][lane] = myd; s_mi[ql][lane] = myi; }
    __syncthreads();
    if (h == 0) {
        #pragma unroll 4
        for (int r = 0; r < 32; ++r) {
            float dc = s_md[ql][r];
            if (dc < worst) {
                int ic = s_mi[ql][r];
                if (lane == wlane) { myd = dc; myi = ic; }
                float v = myd; int pos = lane;
                #pragma unroll
                for (int off = 16; off; off >>= 1) {
                    float ov = __shfl_xor_sync(0xffffffffu, v, off);
                    int   op = __shfl_xor_sync(0xffffffffu, pos, off);
                    if (ov > v || (ov == v && op < pos)) { v = ov; pos = op; }
                }
                worst = v; wlane = pos;
            }
        }
        g_idx[q*32 + lane] = myi;
    }
}

// ---------------- k_gemm0: FFMA2, Y0T[b][n][64] per distinct point ----------
#define XS 132
__global__ void __launch_bounds__(128) k_gemm0(const float* __restrict__ feats) {
    float* smem = (float*)s_raw;
    float* shx = smem + 512;
    float* shw = smem + 512 + 64*XS;
    int tid = threadIdx.x;
    int tx = tid & 15, ty = tid >> 4;
    int b  = blockIdx.x >> 7;
    int n0 = (blockIdx.x & 127) * 128;
    {
        const float4* src = (const float4*)(g_scr + OFF_WD);
        float4* dst = (float4*)shw;
        #pragma unroll
        for (int i = tid; i < 2048; i += 128) dst[i] = src[i];
    }
    {
        const float* fb = feats + (size_t)b*CC*NN + n0;
        #pragma unroll
        for (int i = tid; i < 2048; i += 128) {
            int kk = i >> 5, c4 = i & 31;
            *(float4*)(shx + kk*XS + c4*4) = *(const float4*)(fb + (size_t)kk*NN + c4*4);
        }
    }
    __syncthreads();
    ull acc[8][4];
    #pragma unroll
    for (int r = 0; r < 8; ++r)
        #pragma unroll
        for (int p = 0; p < 4; ++p) acc[r][p] = 0ull;
    #pragma unroll 4
    for (int kk = 0; kk < 64; ++kk) {
        const float* xrow = shx + kk*XS + 2*tx;
        ull x0 = *(const ull*)(xrow);
        ull x1 = *(const ull*)(xrow + 32);
        ull x2 = *(const ull*)(xrow + 64);
        ull x3 = *(const ull*)(xrow + 96);
        const ulonglong2* wrow = (const ulonglong2*)(shw + kk*128 + ty*16);
        #pragma unroll
        for (int j = 0; j < 4; ++j) {
            ulonglong2 wp = wrow[j];
            FX2(acc[2*j  ][0], wp.x, x0); FX2(acc[2*j  ][1], wp.x, x1);
            FX2(acc[2*j  ][2], wp.x, x2); FX2(acc[2*j  ][3], wp.x, x3);
            FX2(acc[2*j+1][0], wp.y, x0); FX2(acc[2*j+1][1], wp.y, x1);
            FX2(acc[2*j+1][2], wp.y, x2); FX2(acc[2*j+1][3], wp.y, x3);
        }
    }
    float v[4][2][8];
    #pragma unroll
    for (int r = 0; r < 8; ++r)
        #pragma unroll
        for (int p = 0; p < 4; ++p) {
            float lo, hi; UNPK(lo, hi, acc[r][p]);
            v[p][0][r] = lo; v[p][1][r] = hi;
        }
    #pragma unroll
    for (int p = 0; p < 4; ++p)
        #pragma unroll
        for (int e = 0; e < 2; ++e) {
            int n_g = n0 + 32*p + 2*tx + e;
            float* dst = g_scr + OFF_Y0T + ((size_t)(b*NN + n_g))*64 + ty*8;
            *(float4*)dst       = make_float4(v[p][e][0], v[p][e][1], v[p][e][2], v[p][e][3]);
            *(float4*)(dst + 4) = make_float4(v[p][e][4], v[p][e][5], v[p][e][6], v[p][e][7]);
        }
}

// ---------------- k_stats1: BN0 stats over virtual Z1 ----------------
__global__ void __launch_bounds__(256) k_stats1(const float* __restrict__ w0raw) {
    int warp = blockIdx.x*8 + (threadIdx.x >> 5);
    int lane = threadIdx.x & 31;
    int m0 = 2*lane;
    float wa0 = w0raw[m0*67 + 64],     wb0 = w0raw[m0*67 + 65],     wc0 = w0raw[m0*67 + 66];
    float wa1 = w0raw[(m0+1)*67 + 64], wb1 = w0raw[(m0+1)*67 + 65], wc1 = w0raw[(m0+1)*67 + 66];
    const float4* xt = (const float4*)(g_scr + OFF_XYZT);
    const float4* nx = (const float4*)(g_scr + OFF_NXYZT);
    float s0 = 0.f, q0 = 0.f, s1 = 0.f, q1 = 0.f;
    int base = warp*128;
    float4 qc = make_float4(0,0,0,0);
    int b = 0, s = 0;
    for (int j = 0; j < 128; ++j) {
        int col = base + j;
        int G = col >> 5, k = col & 31;
        if ((j & 31) == 0) { s = G & (SS-1); b = G >> 12; qc = nx[(size_t)b*SS + s]; }
        int n = g_idx[s*32 + k];
        float4 p = xt[(size_t)b*NN + n];
        float rx = p.x - qc.x, ry = p.y - qc.y, rz = p.z - qc.z;
        float2 y = *(const float2*)(g_scr + OFF_Y0T + ((size_t)(b*NN + n))*64 + m0);
        float z0 = fmaf(wa0, rx, fmaf(wb0, ry, fmaf(wc0, rz, y.x)));
        float z1 = fmaf(wa1, rx, fmaf(wb1, ry, fmaf(wc1, rz, y.y)));
        s0 += z0; q0 = fmaf(z0, z0, q0);
        s1 += z1; q1 = fmaf(z1, z1, q1);
    }
    int bkt = warp & 31;
    atomicAdd(&g_ps[0][bkt][m0],   s0); atomicAdd(&g_pq[0][bkt][m0],   q0);
    atomicAdd(&g_ps[0][bkt][m0+1], s1); atomicAdd(&g_pq[0][bkt][m0+1], q1);
}

// ---------------- k_mma1: HMMA, Z(blob) = W1 @ relu(bn0(gather+rank3)) ----------
// smem: par f32[320]@0 | A u32[4096]@1536 | BH u32[4608]@17920 | BL@36352 (54784B)
__global__ void __launch_bounds__(128) k_mma1(const float* __restrict__ w0raw) {
    char* smem = s_raw;
    float*    sm_par = (float*)smem;
    uint32_t* Asm = (uint32_t*)(smem + 1536);
    uint32_t* BH  = (uint32_t*)(smem + 17920);
    uint32_t* BL  = (uint32_t*)(smem + 36352);
    int tid = threadIdx.x, lane = tid & 31, w = tid >> 5;
    int g = lane >> 2, tig = lane & 3;

    {   // A-fragment image (hi+lo) -> smem
        const uint4* src = (const uint4*)((const uint32_t*)(g_scr + OFF_WD) + 16384);
        uint4* dst = (uint4*)Asm;
        #pragma unroll
        for (int i = tid; i < 1024; i += 128) dst[i] = src[i];
    }
    if (tid < 64) {
        sm_par[tid]       = w0raw[tid*67 + 64];
        sm_par[64 + tid]  = w0raw[tid*67 + 65];
        sm_par[128 + tid] = w0raw[tid*67 + 66];
        sm_par[192 + tid] = g_bna[tid];
        sm_par[256 + tid] = g_bnc[tid];
    }
    __syncthreads();

    {   // B build: one thread per column; BN0+ReLU+hi/lo split, frag layout
        int col = blockIdx.x*128 + tid;
        int G = col >> 5, k = col & 31;
        int s = G & (SS-1), b = G >> 12;
        int n = g_idx[s*32 + k];
        const float4* fr = (const float4*)(g_scr + OFF_Y0T + ((size_t)(b*NN + n))*64);
        float4 p  = ((const float4*)(g_scr + OFF_XYZT))[(size_t)b*NN + n];
        float4 qc = ((const float4*)(g_scr + OFF_NXYZT))[(size_t)b*SS + s];
        float rx = p.x - qc.x, ry = p.y - qc.y, rz = p.z - qc.z;
        #pragma unroll
        for (int i = 0; i < 16; ++i) {
            float4 y = fr[i];
            float yy[4] = {y.x, y.y, y.z, y.w};
            #pragma unroll
            for (int h = 0; h < 2; ++h) {
                int m0 = 4*i + 2*h;
                float z0 = fmaf(sm_par[m0], rx, fmaf(sm_par[64+m0], ry, fmaf(sm_par[128+m0], rz, yy[2*h])));
                z0 = fmaxf(fmaf(sm_par[192+m0], z0, sm_par[256+m0]), 0.f);
                int m1 = m0 + 1;
                float z1 = fmaf(sm_par[m1], rx, fmaf(sm_par[64+m1], ry, fmaf(sm_par[128+m1], rz, yy[2*h+1])));
                z1 = fmaxf(fmaf(sm_par[192+m1], z1, sm_par[256+m1]), 0.f);
                __nv_bfloat16 h0 = __float2bfloat16_rn(z0), h1 = __float2bfloat16_rn(z1);
                float f0 = __bfloat162float(h0), f1 = __bfloat162float(h1);
                int kp = 2*i + h;
                BH[tid*36 + kp] = pack2bf16(f0, f1);
                BL[tid*36 + kp] = pack2bf16(z0 - f0, z1 - f1);
            }
        }
    }
    __syncthreads();

    float acc[16][4];
    #pragma unroll
    for (int tt = 0; tt < 16; ++tt)
        #pragma unroll
        for (int c = 0; c < 4; ++c) acc[tt][c] = 0.f;

    #pragma unroll
    for (int ks = 0; ks < 4; ++ks) {
        uint4 ah = *(const uint4*)(Asm + w*512 + ks*128 + lane*4);
        uint4 al = *(const uint4*)(Asm + 2048 + w*512 + ks*128 + lane*4);
        #pragma unroll
        for (int tt = 0; tt < 16; ++tt) {
            int ba = (tt*8 + g)*36 + ks*8 + tig;
            uint32_t b0h = BH[ba], b1h = BH[ba + 4];
            uint32_t b0l = BL[ba], b1l = BL[ba + 4];
            MMA(acc[tt], ah, b0h, b1h);
            MMA(acc[tt], al, b0h, b1h);
            MMA(acc[tt], ah, b0l, b1l);
        }
    }

    // epilogue: blob store + stats
    float4* zb = (float4*)(g_scr + OFF_Z) + (size_t)blockIdx.x*2048;
    float sg = 0.f, qg = 0.f, s8 = 0.f, q8 = 0.f;
    #pragma unroll
    for (int tt = 0; tt < 16; ++tt) {
        zb[tt*128 + w*32 + lane] = make_float4(acc[tt][0], acc[tt][1], acc[tt][2], acc[tt][3]);
        sg += acc[tt][0] + acc[tt][1];
        qg = fmaf(acc[tt][0], acc[tt][0], fmaf(acc[tt][1], acc[tt][1], qg));
        s8 += acc[tt][2] + acc[tt][3];
        q8 = fmaf(acc[tt][2], acc[tt][2], fmaf(acc[tt][3], acc[tt][3], q8));
    }
    #pragma unroll
    for (int o = 2; o; o >>= 1) {
        sg += __shfl_down_sync(0xffffffffu, sg, o, 4);
        qg += __shfl_down_sync(0xffffffffu, qg, o, 4);
        s8 += __shfl_down_sync(0xffffffffu, s8, o, 4);
        q8 += __shfl_down_sync(0xffffffffu, q8, o, 4);
    }
    if (tig == 0) {
        int bkt = blockIdx.x & 31;
        int m = w*16 + g;
        atomicAdd(&g_ps[1][bkt][m],     sg); atomicAdd(&g_pq[1][bkt][m],     qg);
        atomicAdd(&g_ps[1][bkt][m + 8], s8); atomicAdd(&g_pq[1][bkt][m + 8], q8);
    }
}

// ---------------- k_mma2: HMMA, maxpool(relu(bn2(W2 @ relu(bn1(Zblob))))) ------
// smem: bna[64]@0 bnc[64]@256 | A u32[8192]@512 | BH@33280 | BL@51712 (70144B)
__global__ void __launch_bounds__(256) k_mma2() {
    char* smem = s_raw;
    float*    bna = (float*)smem;
    float*    bnc = (float*)(smem + 256);
    uint32_t* Asm = (uint32_t*)(smem + 512);
    uint32_t* BH  = (uint32_t*)(smem + 33280);
    uint32_t* BL  = (uint32_t*)(smem + 51712);
    int tid = threadIdx.x, lane = tid & 31, w = tid >> 5;
    int g = lane >> 2, tig = lane & 3;

    {
        const uint4* src = (const uint4*)((const uint32_t*)(g_scr + OFF_WD) + 20480);
        uint4* dst = (uint4*)Asm;
        #pragma unroll
        for (int i = tid; i < 2048; i += 256) dst[i] = src[i];
    }
    if (tid < 64) { bna[tid] = g_bna[128 + tid]; bnc[tid] = g_bnc[128 + tid]; }
    __syncthreads();

    {   // prologue: decode blob -> BN1/ReLU -> hi/lo B fragments
        const float* zb = g_scr + OFF_Z + (size_t)blockIdx.x*8192;
        #pragma unroll
        for (int j = 0; j < 16; ++j) {
            int p = j*256 + tid;
            int ptig = p & 3, c = (p >> 2) & 3, gh = (p >> 4) & 3;
            int w1 = (p >> 6) & 3, tt = p >> 8;
            int i0 = tt*512 + w1*128 + gh*32 + ptig*4 + c;
            float z0 = zb[i0], z1 = zb[i0 + 16];
            int kch = w1*16 + 2*gh + 8*(c >> 1);
            z0 = fmaxf(fmaf(bna[kch],     z0, bnc[kch]),     0.f);
            z1 = fmaxf(fmaf(bna[kch + 1], z1, bnc[kch + 1]), 0.f);
            __nv_bfloat16 h0 = __float2bfloat16_rn(z0), h1 = __float2bfloat16_rn(z1);
            float f0 = __bfloat162float(h0), f1 = __bfloat162float(h1);
            int col = tt*8 + ptig*2 + (c & 1);
            int kp  = w1*8 + gh + 4*(c >> 1);
            BH[col*36 + kp] = pack2bf16(f0, f1);
            BL[col*36 + kp] = pack2bf16(z0 - f0, z1 - f1);
        }
    }
    __syncthreads();

    float acc[16][4];
    #pragma unroll
    for (int tt = 0; tt < 16; ++tt)
        #pragma unroll
        for (int c = 0; c < 4; ++c) acc[tt][c] = 0.f;

    #pragma unroll
    for (int ks = 0; ks < 4; ++ks) {
        uint4 ah = *(const uint4*)(Asm + w*512 + ks*128 + lane*4);
        uint4 al = *(const uint4*)(Asm + 4096 + w*512 + ks*128 + lane*4);
        #pragma unroll
        for (int tt = 0; tt < 16; ++tt) {
            int ba = (tt*8 + g)*36 + ks*8 + tig;
            uint32_t b0h = BH[ba], b1h = BH[ba + 4];
            uint32_t b0l = BL[ba], b1l = BL[ba + 4];
            MMA(acc[tt], ah, b0h, b1h);
            MMA(acc[tt], al, b0h, b1h);
            MMA(acc[tt], ah, b0l, b1l);
        }
    }

    // epilogue: per-32-col max/min pools + stats
    float2* mm = (float2*)(g_scr + OFF_MM);
    float sg = 0.f, qg = 0.f, s8 = 0.f, q8 = 0.f;
    #pragma unroll
    for (int p = 0; p < 4; ++p) {
        float mxg = -INF_F, mng = INF_F, mx8 = -INF_F, mn8 = INF_F;
        #pragma unroll
        for (int t4 = 0; t4 < 4; ++t4) {
            int tt = p*4 + t4;
            mxg = fmaxf(mxg, fmaxf(acc[tt][0], acc[tt][1]));
            mng = fminf(mng, fminf(acc[tt][0], acc[tt][1]));
            mx8 = fmaxf(mx8, fmaxf(acc[tt][2], acc[tt][3]));
            mn8 = fminf(mn8, fminf(acc[tt][2], acc[tt][3]));
            sg += acc[tt][0] + acc[tt][1];
            qg = fmaf(acc[tt][0], acc[tt][0], fmaf(acc[tt][1], acc[tt][1], qg));
            s8 += acc[tt][2] + acc[tt][3];
            q8 = fmaf(acc[tt][2], acc[tt][2], fmaf(acc[tt][3], acc[tt][3], q8));
        }
        #pragma unroll
        for (int o = 2; o; o >>= 1) {
            mxg = fmaxf(mxg, __shfl_down_sync(0xffffffffu, mxg, o, 4));
            mng = fminf(mng, __shfl_down_sync(0xffffffffu, mng, o, 4));
            mx8 = fmaxf(mx8, __shfl_down_sync(0xffffffffu, mx8, o, 4));
            mn8 = fminf(mn8, __shfl_down_sync(0xffffffffu, mn8, o, 4));
        }
        if (tig == 0) {
            int m = w*16 + g;
            mm[(size_t)m*NGRP + blockIdx.x*4 + p]       = make_float2(mxg, mng);
            mm[(size_t)(m + 8)*NGRP + blockIdx.x*4 + p] = make_float2(mx8, mn8);
        }
    }
    #pragma unroll
    for (int o = 2; o; o >>= 1) {
        sg += __shfl_down_sync(0xffffffffu, sg, o, 4);
        qg += __shfl_down_sync(0xffffffffu, qg, o, 4);
        s8 += __shfl_down_sync(0xffffffffu, s8, o, 4);
        q8 += __shfl_down_sync(0xffffffffu, q8, o, 4);
    }
    if (tig == 0) {
        int bkt = blockIdx.x & 31;
        int m = w*16 + g;
        atomicAdd(&g_ps[2][bkt][m],     sg); atomicAdd(&g_pq[2][bkt][m],     qg);
        atomicAdd(&g_ps[2][bkt][m + 8], s8); atomicAdd(&g_pq[2][bkt][m + 8], q8);
    }
}

// ---------------- BN affine params ----------------
__global__ void k_bnparam(int slot, const float* __restrict__ g,
                          const float* __restrict__ b, int M) {
    int m = threadIdx.x;
    if (m >= M) return;
    float s = 0.f, q = 0.f;
    #pragma unroll
    for (int j = 0; j < 32; ++j) { s += g_ps[slot][j][m]; q += g_pq[slot][j][m]; }
    const float cnt = (float)NCOL;
    float mu  = s / cnt;
    float var = q / cnt - mu*mu;
    float a = g[m] * rsqrtf(var + BN_EPS);
    g_bna[slot*128 + m] = a;
    g_bnc[slot*128 + m] = b[m] - mu*a;
}

// ---------------- finalize ----------------
__global__ void __launch_bounds__(256) k_final(float* __restrict__ out) {
    int t = blockIdx.x*256 + threadIdx.x;
    if (t >= BB*128*SS) return;
    int s  = t & (SS-1);
    int bc = t >> 12;
    int c = bc & 127, b = bc >> 7;
    float a  = g_bna[2*128 + c];
    float cc = g_bnc[2*128 + c];
    const float2* mm = (const float2*)(g_scr + OFF_MM);
    float2 e = mm[(size_t)c*NGRP + b*SS + s];
    float z = (a >= 0.f) ? e.x : e.y;
    out[BB*3*SS + t] = fmaxf(fmaf(a, z, cc), 0.f);
}

// ---------------- launch ----------------
extern "C" void kernel_launch(void* const* d_in, const int* in_sizes, int n_in,
                              void* d_out, int out_size) {
    (void)in_sizes; (void)n_in; (void)out_size;
    const float* xyz   = (const float*)d_in[0];
    const float* feats = (const float*)d_in[1];
    const int*   perm  = (const int*)d_in[2];
    const float* w0 = (const float*)d_in[3];
    const float* g0 = (const float*)d_in[4];
    const float* b0 = (const float*)d_in[5];
    const float* w1 = (const float*)d_in[6];
    const float* g1 = (const float*)d_in[7];
    const float* b1 = (const float*)d_in[8];
    const float* w2 = (const float*)d_in[9];
    const float* g2 = (const float*)d_in[10];
    const float* b2 = (const float*)d_in[11];
    float* out = (float*)d_out;

    const int sm0  = (512 + 64*XS + 64*128) * 4;   // 68608 (gemm0)
    const int smm1 = 54784;
    const int smm2 = 70144;
    cudaFuncSetAttribute(k_gemm0, cudaFuncAttributeMaxDynamicSharedMemorySize, sm0);
    cudaFuncSetAttribute(k_mma1,  cudaFuncAttributeMaxDynamicSharedMemorySize, smm1);
    cudaFuncSetAttribute(k_mma2,  cudaFuncAttributeMaxDynamicSharedMemorySize, smm2);

    k_prep0 <<<(BB*NN)/256, 256>>>(xyz, perm, out);
    k_prepw <<<64, 256>>>(w0, w1, w2);
    k_knn   <<<SS/8, 512>>>();
    k_gemm0 <<<BB*NN/128, 128, sm0>>>(feats);
    k_stats1<<<NCOL/1024, 256>>>(w0);
    k_bnparam<<<1,128>>>(0, g0, b0, 64);
    k_mma1  <<<NCOL/128, 128, smm1>>>(w0);
    k_bnparam<<<1,128>>>(1, g1, b1, 64);
    k_mma2  <<<NCOL/128, 256, smm2>>>();
    k_bnparam<<<1,128>>>(2, g2, b2, 128);
    k_final<<<(BB*128*SS)/256, 256>>>(out);
}

// round 14
// speedup vs baseline: 1.0310x; 1.0235x over previous
#include <cuda_runtime.h>
#include <cuda_bf16.h>
#include <math.h>
#include <stdint.h>

// ---------------- problem constants ----------------
#define BB 8
#define NN 16384
#define SS 4096
#define KK 32
#define CC 64
#define NCOL (BB*SS*KK)          // 1048576 columns
#define NGRP (NCOL/32)           // 32768 (b,s) groups
#define BN_EPS 1e-5f
#define INF_F 3.0e38f

// ---------------- scratch layout (floats) ----------------
#define OFF_Y0T     ((size_t)0)           // (B,N,64)
#define OFF_XYZT    ((size_t)8388608)     // (B,N,4)
#define OFF_NXYZT   ((size_t)8912896)     // (B,S,4)
#define OFF_Z       ((size_t)9043968)     // fragment-blob Z: 8192 blocks x 8192 f32
#define OFF_MM      ((size_t)76152832)    // 128 x NGRP float2
#define OFF_WD      ((size_t)84541440)    // w0 dup image + HMMA A-fragment images
#define SCR_TOTAL   ((size_t)84590592)

__device__ float g_scr[SCR_TOTAL];
__device__ int   g_idx[SS*KK];
__device__ float g_ps[3][32][128];
__device__ float g_pq[3][32][128];
__device__ float g_bna[3*128];
__device__ float g_bnc[3*128];

// single shared symbol; kernels cast locally
extern __shared__ char s_raw[];

static __device__ __forceinline__ int clampN(int n) {
    return n < 0 ? 0 : (n >= NN ? NN-1 : n);
}

typedef unsigned long long ull;
#define FX2(acc, w, x) \
    asm("fma.rn.f32x2 %0, %1, %2, %0;" : "+l"(acc) : "l"(w), "l"(x))
#define UNPK(lo, hi, p) \
    asm("mov.b64 {%0, %1}, %2;" : "=f"(lo), "=f"(hi) : "l"(p))

__device__ __forceinline__ uint32_t pack2bf16(float a, float b) {
    __nv_bfloat162 h = __floats2bfloat162_rn(a, b);
    return *(uint32_t*)&h;
}

// HMMA m16n8k16 bf16 -> f32
#define MMA(acc, a, b0, b1) \
    asm("mma.sync.aligned.m16n8k16.row.col.f32.bf16.bf16.f32 " \
        "{%0,%1,%2,%3}, {%4,%5,%6,%7}, {%8,%9}, {%0,%1,%2,%3};" \
        : "+f"((acc)[0]), "+f"((acc)[1]), "+f"((acc)[2]), "+f"((acc)[3]) \
        : "r"((a).x), "r"((a).y), "r"((a).z), "r"((a).w), "r"(b0), "r"(b1))

// ---------------- prep: new_xyz + query coords + clear stats ----------------
__global__ void __launch_bounds__(256) k_newxyz(const float* __restrict__ xyz,
                                                const int* __restrict__ perm,
                                                float* __restrict__ out) {
    int t = blockIdx.x*256 + threadIdx.x;
    if (t < 3*32*128) { ((float*)g_ps)[t] = 0.f; ((float*)g_pq)[t] = 0.f; }
    if (t >= BB*SS) return;
    int b = t / SS, s = t % SS;
    int n = clampN(perm[s]);
    #pragma unroll
    for (int c = 0; c < 3; ++c) {
        float v = xyz[((size_t)b*3 + c)*NN + n];
        out[((size_t)b*3 + c)*SS + s] = v;
        g_scr[OFF_NXYZT + ((size_t)(b*SS + s))*4 + c] = v;
    }
    g_scr[OFF_NXYZT + ((size_t)(b*SS + s))*4 + 3] = 0.f;
}

// ---------------- prep: xyz transpose ----------------
__global__ void __launch_bounds__(256) k_xyzt(const float* __restrict__ xyz) {
    int t = blockIdx.x*256 + threadIdx.x;
    if (t >= BB*NN) return;
    int b = t >> 14, n = t & (NN-1);
    #pragma unroll
    for (int c = 0; c < 3; ++c)
        g_scr[OFF_XYZT + ((size_t)(b*NN + n))*4 + c] = xyz[((size_t)b*3 + c)*NN + n];
    g_scr[OFF_XYZT + ((size_t)(b*NN + n))*4 + 3] = 0.f;
}

// ---------------- prep: w0 dup image + HMMA A-fragment images (hi/lo) ----------
__global__ void __launch_bounds__(256) k_prepw(const float* __restrict__ w0,
                                               const float* __restrict__ w1,
                                               const float* __restrict__ w2) {
    int t = blockIdx.x*256 + threadIdx.x;
    if (t >= 16384) return;
    if (t < 4096) {                      // gemm0 dup-pair image (w0[:, :64])
        int m = t >> 6, kk = t & 63;
        float v = w0[m*67 + kk];
        float* dst = g_scr + OFF_WD + (size_t)kk*128 + 2*m;
        dst[0] = v; dst[1] = v;
        return;
    }
    const float* W; uint32_t* base; int NW, u;
    uint32_t* wf = (uint32_t*)(g_scr + OFF_WD);
    if (t < 8192) { W = w1; NW = 4; u = t - 4096; base = wf + 16384; }
    else          { W = w2; NW = 8; u = t - 8192; base = wf + 20480; }
    int pass = u / (NW*512);
    int rest = u - pass*NW*512;
    int w = rest >> 9, ks = (rest >> 7) & 3, l = (rest >> 2) & 31, reg = rest & 3;
    int g = l >> 2, tig = l & 3;
    int m = w*16 + g + 8*(reg & 1);
    int k = ks*16 + tig*2 + 8*(reg >> 1);
    float v0 = W[m*64 + k], v1 = W[m*64 + k + 1];
    __nv_bfloat16 h0 = __float2bfloat16_rn(v0), h1 = __float2bfloat16_rn(v1);
    float f0 = __bfloat162float(h0), f1 = __bfloat162float(h1);
    base[u] = (pass == 0) ? pack2bf16(f0, f1) : pack2bf16(v0 - f0, v1 - f1);
}

// ---------------- KNN (round-10 exact: 1 warp/query, 8 q/block) ----------------
__global__ void __launch_bounds__(256) k_knn() {
    __shared__ float4 s_tile[2048];
    int tid = threadIdx.x;
    int w = tid >> 5, lane = tid & 31;
    int q = blockIdx.x*8 + w;
    const float4* xt = (const float4*)(g_scr + OFF_XYZT);
    float4 qp = ((const float4*)(g_scr + OFF_NXYZT))[q];
    float qq = qp.x*qp.x + qp.y*qp.y + qp.z*qp.z;
    float myd = INF_F; int myi = 0;
    float worst = INF_F; int wlane = 0;
    for (int tile = 0; tile < 8; ++tile) {
        __syncthreads();
        for (int i = tid; i < 2048; i += 256) {
            float4 p = xt[tile*2048 + i];
            p.w = p.x*p.x + p.y*p.y + p.z*p.z;
            s_tile[i] = p;
        }
        __syncthreads();
        #pragma unroll 4
        for (int j = 0; j < 64; ++j) {
            int ii = j*32 + lane;
            float4 p = s_tile[ii];
            float d = qq - 2.f*(qp.x*p.x + qp.y*p.y + qp.z*p.z) + p.w;
            int idx = tile*2048 + ii;
            unsigned hits = __ballot_sync(0xffffffffu, d < worst);
            while (hits) {
                int src = __ffs(hits) - 1;
                hits &= hits - 1;
                float dc = __shfl_sync(0xffffffffu, d, src);
                int   ic = __shfl_sync(0xffffffffu, idx, src);
                if (dc < worst) {
                    if (lane == wlane) { myd = dc; myi = ic; }
                    float v = myd; int pos = lane;
                    #pragma unroll
                    for (int off = 16; off; off >>= 1) {
                        float ov = __shfl_xor_sync(0xffffffffu, v, off);
                        int   op = __shfl_xor_sync(0xffffffffu, pos, off);
                        if (ov > v || (ov == v && op < pos)) { v = ov; pos = op; }
                    }
                    worst = v; wlane = pos;
                }
            }
        }
    }
    g_idx[q*32 + lane] = myi;
}

// ---------------- k_gemm0: FFMA2, Y0T[b][n][64] per distinct point ----------
#define XS 132
__global__ void __launch_bounds__(128) k_gemm0(const float* __restrict__ feats) {
    float* smem = (float*)s_raw;
    float* shx = smem + 512;
    float* shw = smem + 512 + 64*XS;
    int tid = threadIdx.x;
    int tx = tid & 15, ty = tid >> 4;
    int b  = blockIdx.x >> 7;
    int n0 = (blockIdx.x & 127) * 128;
    {
        const float4* src = (const float4*)(g_scr + OFF_WD);
        float4* dst = (float4*)shw;
        #pragma unroll
        for (int i = tid; i < 2048; i += 128) dst[i] = src[i];
    }
    {
        const float* fb = feats + (size_t)b*CC*NN + n0;
        #pragma unroll
        for (int i = tid; i < 2048; i += 128) {
            int kk = i >> 5, c4 = i & 31;
            *(float4*)(shx + kk*XS + c4*4) = *(const float4*)(fb + (size_t)kk*NN + c4*4);
        }
    }
    __syncthreads();
    ull acc[8][4];
    #pragma unroll
    for (int r = 0; r < 8; ++r)
        #pragma unroll
        for (int p = 0; p < 4; ++p) acc[r][p] = 0ull;
    #pragma unroll 4
    for (int kk = 0; kk < 64; ++kk) {
        const float* xrow = shx + kk*XS + 2*tx;
        ull x0 = *(const ull*)(xrow);
        ull x1 = *(const ull*)(xrow + 32);
        ull x2 = *(const ull*)(xrow + 64);
        ull x3 = *(const ull*)(xrow + 96);
        const ulonglong2* wrow = (const ulonglong2*)(shw + kk*128 + ty*16);
        #pragma unroll
        for (int j = 0; j < 4; ++j) {
            ulonglong2 wp = wrow[j];
            FX2(acc[2*j  ][0], wp.x, x0); FX2(acc[2*j  ][1], wp.x, x1);
            FX2(acc[2*j  ][2], wp.x, x2); FX2(acc[2*j  ][3], wp.x, x3);
            FX2(acc[2*j+1][0], wp.y, x0); FX2(acc[2*j+1][1], wp.y, x1);
            FX2(acc[2*j+1][2], wp.y, x2); FX2(acc[2*j+1][3], wp.y, x3);
        }
    }
    float v[4][2][8];
    #pragma unroll
    for (int r = 0; r < 8; ++r)
        #pragma unroll
        for (int p = 0; p < 4; ++p) {
            float lo, hi; UNPK(lo, hi, acc[r][p]);
            v[p][0][r] = lo; v[p][1][r] = hi;
        }
    #pragma unroll
    for (int p = 0; p < 4; ++p)
        #pragma unroll
        for (int e = 0; e < 2; ++e) {
            int n_g = n0 + 32*p + 2*tx + e;
            float* dst = g_scr + OFF_Y0T + ((size_t)(b*NN + n_g))*64 + ty*8;
            *(float4*)dst       = make_float4(v[p][e][0], v[p][e][1], v[p][e][2], v[p][e][3]);
            *(float4*)(dst + 4) = make_float4(v[p][e][4], v[p][e][5], v[p][e][6], v[p][e][7]);
        }
}

// ---------------- k_stats1: BN0 stats over virtual Z1 ----------------
__global__ void __launch_bounds__(256) k_stats1(const float* __restrict__ w0raw) {
    int warp = blockIdx.x*8 + (threadIdx.x >> 5);
    int lane = threadIdx.x & 31;
    int m0 = 2*lane;
    float wa0 = w0raw[m0*67 + 64],     wb0 = w0raw[m0*67 + 65],     wc0 = w0raw[m0*67 + 66];
    float wa1 = w0raw[(m0+1)*67 + 64], wb1 = w0raw[(m0+1)*67 + 65], wc1 = w0raw[(m0+1)*67 + 66];
    const float4* xt = (const float4*)(g_scr + OFF_XYZT);
    const float4* nx = (const float4*)(g_scr + OFF_NXYZT);
    float s0 = 0.f, q0 = 0.f, s1 = 0.f, q1 = 0.f;
    int base = warp*128;
    float4 qc = make_float4(0,0,0,0);
    int b = 0, s = 0;
    for (int j = 0; j < 128; ++j) {
        int col = base + j;
        int G = col >> 5, k = col & 31;
        if ((j & 31) == 0) { s = G & (SS-1); b = G >> 12; qc = nx[(size_t)b*SS + s]; }
        int n = g_idx[s*32 + k];
        float4 p = xt[(size_t)b*NN + n];
        float rx = p.x - qc.x, ry = p.y - qc.y, rz = p.z - qc.z;
        float2 y = *(const float2*)(g_scr + OFF_Y0T + ((size_t)(b*NN + n))*64 + m0);
        float z0 = fmaf(wa0, rx, fmaf(wb0, ry, fmaf(wc0, rz, y.x)));
        float z1 = fmaf(wa1, rx, fmaf(wb1, ry, fmaf(wc1, rz, y.y)));
        s0 += z0; q0 = fmaf(z0, z0, q0);
        s1 += z1; q1 = fmaf(z1, z1, q1);
    }
    int bkt = warp & 31;
    atomicAdd(&g_ps[0][bkt][m0],   s0); atomicAdd(&g_pq[0][bkt][m0],   q0);
    atomicAdd(&g_ps[0][bkt][m0+1], s1); atomicAdd(&g_pq[0][bkt][m0+1], q1);
}

// ---------------- k_mma1: HMMA, Z(blob) = W1 @ relu(bn0(gather+rank3)) ----------
// smem: par f32[320]@0 | A u32[4096]@1536 | BH u32[4608]@17920 | BL@36352 (54784B)
__global__ void __launch_bounds__(128) k_mma1(const float* __restrict__ w0raw) {
    char* smem = s_raw;
    float*    sm_par = (float*)smem;
    uint32_t* Asm = (uint32_t*)(smem + 1536);
    uint32_t* BH  = (uint32_t*)(smem + 17920);
    uint32_t* BL  = (uint32_t*)(smem + 36352);
    int tid = threadIdx.x, lane = tid & 31, w = tid >> 5;
    int g = lane >> 2, tig = lane & 3;

    {   // A-fragment image (hi+lo) -> smem
        const uint4* src = (const uint4*)((const uint32_t*)(g_scr + OFF_WD) + 16384);
        uint4* dst = (uint4*)Asm;
        #pragma unroll
        for (int i = tid; i < 1024; i += 128) dst[i] = src[i];
    }
    if (tid < 64) {
        sm_par[tid]       = w0raw[tid*67 + 64];
        sm_par[64 + tid]  = w0raw[tid*67 + 65];
        sm_par[128 + tid] = w0raw[tid*67 + 66];
        sm_par[192 + tid] = g_bna[tid];
        sm_par[256 + tid] = g_bnc[tid];
    }
    __syncthreads();

    {   // B build: one thread per column; BN0+ReLU+hi/lo split, frag layout
        int col = blockIdx.x*128 + tid;
        int G = col >> 5, k = col & 31;
        int s = G & (SS-1), b = G >> 12;
        int n = g_idx[s*32 + k];
        const float4* fr = (const float4*)(g_scr + OFF_Y0T + ((size_t)(b*NN + n))*64);
        float4 p  = ((const float4*)(g_scr + OFF_XYZT))[(size_t)b*NN + n];
        float4 qc = ((const float4*)(g_scr + OFF_NXYZT))[(size_t)b*SS + s];
        float rx = p.x - qc.x, ry = p.y - qc.y, rz = p.z - qc.z;
        #pragma unroll
        for (int i = 0; i < 16; ++i) {
            float4 y = fr[i];
            float yy[4] = {y.x, y.y, y.z, y.w};
            #pragma unroll
            for (int h = 0; h < 2; ++h) {
                int m0 = 4*i + 2*h;
                float z0 = fmaf(sm_par[m0], rx, fmaf(sm_par[64+m0], ry, fmaf(sm_par[128+m0], rz, yy[2*h])));
                z0 = fmaxf(fmaf(sm_par[192+m0], z0, sm_par[256+m0]), 0.f);
                int m1 = m0 + 1;
                float z1 = fmaf(sm_par[m1], rx, fmaf(sm_par[64+m1], ry, fmaf(sm_par[128+m1], rz, yy[2*h+1])));
                z1 = fmaxf(fmaf(sm_par[192+m1], z1, sm_par[256+m1]), 0.f);
                __nv_bfloat16 h0 = __float2bfloat16_rn(z0), h1 = __float2bfloat16_rn(z1);
                float f0 = __bfloat162float(h0), f1 = __bfloat162float(h1);
                int kp = 2*i + h;
                BH[tid*36 + kp] = pack2bf16(f0, f1);
                BL[tid*36 + kp] = pack2bf16(z0 - f0, z1 - f1);
            }
        }
    }
    __syncthreads();

    float acc[16][4];
    #pragma unroll
    for (int tt = 0; tt < 16; ++tt)
        #pragma unroll
        for (int c = 0; c < 4; ++c) acc[tt][c] = 0.f;

    #pragma unroll
    for (int ks = 0; ks < 4; ++ks) {
        uint4 ah = *(const uint4*)(Asm + w*512 + ks*128 + lane*4);
        uint4 al = *(const uint4*)(Asm + 2048 + w*512 + ks*128 + lane*4);
        #pragma unroll
        for (int tt = 0; tt < 16; ++tt) {
            int ba = (tt*8 + g)*36 + ks*8 + tig;
            uint32_t b0h = BH[ba], b1h = BH[ba + 4];
            uint32_t b0l = BL[ba], b1l = BL[ba + 4];
            MMA(acc[tt], ah, b0h, b1h);
            MMA(acc[tt], al, b0h, b1h);
            MMA(acc[tt], ah, b0l, b1l);
        }
    }

    // epilogue: blob store + stats
    float4* zb = (float4*)(g_scr + OFF_Z) + (size_t)blockIdx.x*2048;
    float sg = 0.f, qg = 0.f, s8 = 0.f, q8 = 0.f;
    #pragma unroll
    for (int tt = 0; tt < 16; ++tt) {
        zb[tt*128 + w*32 + lane] = make_float4(acc[tt][0], acc[tt][1], acc[tt][2], acc[tt][3]);
        sg += acc[tt][0] + acc[tt][1];
        qg = fmaf(acc[tt][0], acc[tt][0], fmaf(acc[tt][1], acc[tt][1], qg));
        s8 += acc[tt][2] + acc[tt][3];
        q8 = fmaf(acc[tt][2], acc[tt][2], fmaf(acc[tt][3], acc[tt][3], q8));
    }
    #pragma unroll
    for (int o = 2; o; o >>= 1) {
        sg += __shfl_down_sync(0xffffffffu, sg, o, 4);
        qg += __shfl_down_sync(0xffffffffu, qg, o, 4);
        s8 += __shfl_down_sync(0xffffffffu, s8, o, 4);
        q8 += __shfl_down_sync(0xffffffffu, q8, o, 4);
    }
    if (tig == 0) {
        int bkt = blockIdx.x & 31;
        int m = w*16 + g;
        atomicAdd(&g_ps[1][bkt][m],     sg); atomicAdd(&g_pq[1][bkt][m],     qg);
        atomicAdd(&g_ps[1][bkt][m + 8], s8); atomicAdd(&g_pq[1][bkt][m + 8], q8);
    }
}

// ---------------- k_mma2: HMMA, maxpool(relu(bn2(W2 @ relu(bn1(Zblob))))) ------
// smem: bna[64]@0 bnc[64]@256 | A u32[8192]@512 | BH@33280 | BL@51712 (70144B)
__global__ void __launch_bounds__(256) k_mma2() {
    char* smem = s_raw;
    float*    bna = (float*)smem;
    float*    bnc = (float*)(smem + 256);
    uint32_t* Asm = (uint32_t*)(smem + 512);
    uint32_t* BH  = (uint32_t*)(smem + 33280);
    uint32_t* BL  = (uint32_t*)(smem + 51712);
    int tid = threadIdx.x, lane = tid & 31, w = tid >> 5;
    int g = lane >> 2, tig = lane & 3;

    {
        const uint4* src = (const uint4*)((const uint32_t*)(g_scr + OFF_WD) + 20480);
        uint4* dst = (uint4*)Asm;
        #pragma unroll
        for (int i = tid; i < 2048; i += 256) dst[i] = src[i];
    }
    if (tid < 64) { bna[tid] = g_bna[128 + tid]; bnc[tid] = g_bnc[128 + tid]; }
    __syncthreads();

    {   // prologue: decode blob -> BN1/ReLU -> hi/lo B fragments
        const float* zb = g_scr + OFF_Z + (size_t)blockIdx.x*8192;
        #pragma unroll
        for (int j = 0; j < 16; ++j) {
            int p = j*256 + tid;
            int ptig = p & 3, c = (p >> 2) & 3, gh = (p >> 4) & 3;
            int w1 = (p >> 6) & 3, tt = p >> 8;
            int i0 = tt*512 + w1*128 + gh*32 + ptig*4 + c;
            float z0 = zb[i0], z1 = zb[i0 + 16];
            int kch = w1*16 + 2*gh + 8*(c >> 1);
            z0 = fmaxf(fmaf(bna[kch],     z0, bnc[kch]),     0.f);
            z1 = fmaxf(fmaf(bna[kch + 1], z1, bnc[kch + 1]), 0.f);
            __nv_bfloat16 h0 = __float2bfloat16_rn(z0), h1 = __float2bfloat16_rn(z1);
            float f0 = __bfloat162float(h0), f1 = __bfloat162float(h1);
            int col = tt*8 + ptig*2 + (c & 1);
            int kp  = w1*8 + gh + 4*(c >> 1);
            BH[col*36 + kp] = pack2bf16(f0, f1);
            BL[col*36 + kp] = pack2bf16(z0 - f0, z1 - f1);
        }
    }
    __syncthreads();

    float acc[16][4];
    #pragma unroll
    for (int tt = 0; tt < 16; ++tt)
        #pragma unroll
        for (int c = 0; c < 4; ++c) acc[tt][c] = 0.f;

    #pragma unroll
    for (int ks = 0; ks < 4; ++ks) {
        uint4 ah = *(const uint4*)(Asm + w*512 + ks*128 + lane*4);
        uint4 al = *(const uint4*)(Asm + 4096 + w*512 + ks*128 + lane*4);
        #pragma unroll
        for (int tt = 0; tt < 16; ++tt) {
            int ba = (tt*8 + g)*36 + ks*8 + tig;
            uint32_t b0h = BH[ba], b1h = BH[ba + 4];
            uint32_t b0l = BL[ba], b1l = BL[ba + 4];
            MMA(acc[tt], ah, b0h, b1h);
            MMA(acc[tt], al, b0h, b1h);
            MMA(acc[tt], ah, b0l, b1l);
        }
    }

    // epilogue: per-32-col max/min pools + stats
    float2* mm = (float2*)(g_scr + OFF_MM);
    float sg = 0.f, qg = 0.f, s8 = 0.f, q8 = 0.f;
    #pragma unroll
    for (int p = 0; p < 4; ++p) {
        float mxg = -INF_F, mng = INF_F, mx8 = -INF_F, mn8 = INF_F;
        #pragma unroll
        for (int t4 = 0; t4 < 4; ++t4) {
            int tt = p*4 + t4;
            mxg = fmaxf(mxg, fmaxf(acc[tt][0], acc[tt][1]));
            mng = fminf(mng, fminf(acc[tt][0], acc[tt][1]));
            mx8 = fmaxf(mx8, fmaxf(acc[tt][2], acc[tt][3]));
            mn8 = fminf(mn8, fminf(acc[tt][2], acc[tt][3]));
            sg += acc[tt][0] + acc[tt][1];
            qg = fmaf(acc[tt][0], acc[tt][0], fmaf(acc[tt][1], acc[tt][1], qg));
            s8 += acc[tt][2] + acc[tt][3];
            q8 = fmaf(acc[tt][2], acc[tt][2], fmaf(acc[tt][3], acc[tt][3], q8));
        }
        #pragma unroll
        for (int o = 2; o; o >>= 1) {
            mxg = fmaxf(mxg, __shfl_down_sync(0xffffffffu, mxg, o, 4));
            mng = fminf(mng, __shfl_down_sync(0xffffffffu, mng, o, 4));
            mx8 = fmaxf(mx8, __shfl_down_sync(0xffffffffu, mx8, o, 4));
            mn8 = fminf(mn8, __shfl_down_sync(0xffffffffu, mn8, o, 4));
        }
        if (tig == 0) {
            int m = w*16 + g;
            mm[(size_t)m*NGRP + blockIdx.x*4 + p]       = make_float2(mxg, mng);
            mm[(size_t)(m + 8)*NGRP + blockIdx.x*4 + p] = make_float2(mx8, mn8);
        }
    }
    #pragma unroll
    for (int o = 2; o; o >>= 1) {
        sg += __shfl_down_sync(0xffffffffu, sg, o, 4);
        qg += __shfl_down_sync(0xffffffffu, qg, o, 4);
        s8 += __shfl_down_sync(0xffffffffu, s8, o, 4);
        q8 += __shfl_down_sync(0xffffffffu, q8, o, 4);
    }
    if (tig == 0) {
        int bkt = blockIdx.x & 31;
        int m = w*16 + g;
        atomicAdd(&g_ps[2][bkt][m],     sg); atomicAdd(&g_pq[2][bkt][m],     qg);
        atomicAdd(&g_ps[2][bkt][m + 8], s8); atomicAdd(&g_pq[2][bkt][m + 8], q8);
    }
}

// ---------------- BN affine params ----------------
__global__ void k_bnparam(int slot, const float* __restrict__ g,
                          const float* __restrict__ b, int M) {
    int m = threadIdx.x;
    if (m >= M) return;
    float s = 0.f, q = 0.f;
    #pragma unroll
    for (int j = 0; j < 32; ++j) { s += g_ps[slot][j][m]; q += g_pq[slot][j][m]; }
    const float cnt = (float)NCOL;
    float mu  = s / cnt;
    float var = q / cnt - mu*mu;
    float a = g[m] * rsqrtf(var + BN_EPS);
    g_bna[slot*128 + m] = a;
    g_bnc[slot*128 + m] = b[m] - mu*a;
}

// ---------------- finalize ----------------
__global__ void __launch_bounds__(256) k_final(float* __restrict__ out) {
    int t = blockIdx.x*256 + threadIdx.x;
    if (t >= BB*128*SS) return;
    int s  = t & (SS-1);
    int bc = t >> 12;
    int c = bc & 127, b = bc >> 7;
    float a  = g_bna[2*128 + c];
    float cc = g_bnc[2*128 + c];
    const float2* mm = (const float2*)(g_scr + OFF_MM);
    float2 e = mm[(size_t)c*NGRP + b*SS + s];
    float z = (a >= 0.f) ? e.x : e.y;
    out[BB*3*SS + t] = fmaxf(fmaf(a, z, cc), 0.f);
}

// ---------------- launch (fork/join: {prepw->gemm0} overlaps {newxyz->xyzt->knn}) ----
extern "C" void kernel_launch(void* const* d_in, const int* in_sizes, int n_in,
                              void* d_out, int out_size) {
    (void)in_sizes; (void)n_in; (void)out_size;
    const float* xyz   = (const float*)d_in[0];
    const float* feats = (const float*)d_in[1];
    const int*   perm  = (const int*)d_in[2];
    const float* w0 = (const float*)d_in[3];
    const float* g0 = (const float*)d_in[4];
    const float* b0 = (const float*)d_in[5];
    const float* w1 = (const float*)d_in[6];
    const float* g1 = (const float*)d_in[7];
    const float* b1 = (const float*)d_in[8];
    const float* w2 = (const float*)d_in[9];
    const float* g2 = (const float*)d_in[10];
    const float* b2 = (const float*)d_in[11];
    float* out = (float*)d_out;

    const int sm0  = (512 + 64*XS + 64*128) * 4;   // 68608 (gemm0)
    const int smm1 = 54784;
    const int smm2 = 70144;

    static cudaStream_t s2 = nullptr;
    static cudaEvent_t e1 = nullptr, e2 = nullptr;
    if (s2 == nullptr) {
        cudaStreamCreateWithFlags(&s2, cudaStreamNonBlocking);
        cudaEventCreateWithFlags(&e1, cudaEventDisableTiming);
        cudaEventCreateWithFlags(&e2, cudaEventDisableTiming);
        cudaFuncSetAttribute(k_gemm0, cudaFuncAttributeMaxDynamicSharedMemorySize, sm0);
        cudaFuncSetAttribute(k_mma1,  cudaFuncAttributeMaxDynamicSharedMemorySize, smm1);
        cudaFuncSetAttribute(k_mma2,  cudaFuncAttributeMaxDynamicSharedMemorySize, smm2);
    }

    // fork: bring s2 into the capture via event dependency on the origin stream
    cudaEventRecord(e1, 0);
    cudaStreamWaitEvent(s2, e1, 0);

    // side stream: weight prep + dedup layer-0 GEMM (independent of xyz path)
    k_prepw <<<64, 256, 0, s2>>>(w0, w1, w2);
    k_gemm0 <<<BB*NN/128, 128, sm0, s2>>>(feats);
    cudaEventRecord(e2, s2);

    // main stream: xyz path + KNN (overlaps with side stream)
    k_newxyz<<<(BB*SS)/256, 256>>>(xyz, perm, out);
    k_xyzt  <<<(BB*NN)/256, 256>>>(xyz);
    k_knn   <<<SS/8, 256>>>();

    // join: stats1 needs gemm0 (Y0T) + knn (g_idx)
    cudaStreamWaitEvent(0, e2, 0);

    k_stats1<<<NCOL/1024, 256>>>(w0);
    k_bnparam<<<1,128>>>(0, g0, b0, 64);
    k_mma1  <<<NCOL/128, 128, smm1>>>(w0);
    k_bnparam<<<1,128>>>(1, g1, b1, 64);
    k_mma2  <<<NCOL/128, 256, smm2>>>();
    k_bnparam<<<1,128>>>(2, g2, b2, 128);
    k_final<<<(BB*128*SS)/256, 256>>>(out);
}

// round 16
// speedup vs baseline: 1.1087x; 1.0753x over previous
#include <cuda_runtime.h>
#include <cuda_bf16.h>
#include <math.h>
#include <stdint.h>

// ---------------- problem constants ----------------
#define BB 8
#define NN 16384
#define SS 4096
#define KK 32
#define CC 64
#define NCOL (BB*SS*KK)          // 1048576 columns
#define NGRP (NCOL/32)           // 32768 (b,s) groups
#define BN_EPS 1e-5f
#define INF_F 3.0e38f

// ---------------- scratch layout (floats) ----------------
#define OFF_Y0T     ((size_t)0)           // (B,N,64)
#define OFF_XYZT    ((size_t)8388608)     // (B,N,4)
#define OFF_NXYZT   ((size_t)8912896)     // (B,S,4)
#define OFF_Z       ((size_t)9043968)     // fragment-blob Z: 8192 blocks x 8192 f32
#define OFF_MM      ((size_t)76152832)    // 128 x NGRP float2
#define OFF_WD      ((size_t)84541440)    // w0 dup image + HMMA A-fragment images
#define SCR_TOTAL   ((size_t)84590592)

__device__ float g_scr[SCR_TOTAL];
__device__ int   g_idx[SS*KK];
__device__ float g_ps[3][32][128];
__device__ float g_pq[3][32][128];
__device__ float g_bna[3*128];
__device__ float g_bnc[3*128];

// single shared symbol; kernels cast locally
extern __shared__ char s_raw[];

static __device__ __forceinline__ int clampN(int n) {
    return n < 0 ? 0 : (n >= NN ? NN-1 : n);
}

typedef unsigned long long ull;
#define FX2(acc, w, x) \
    asm("fma.rn.f32x2 %0, %1, %2, %0;" : "+l"(acc) : "l"(w), "l"(x))
#define UNPK(lo, hi, p) \
    asm("mov.b64 {%0, %1}, %2;" : "=f"(lo), "=f"(hi) : "l"(p))

__device__ __forceinline__ uint32_t pack2bf16(float a, float b) {
    __nv_bfloat162 h = __floats2bfloat162_rn(a, b);
    return *(uint32_t*)&h;
}

// HMMA m16n8k16 bf16 -> f32
#define MMA(acc, a, b0, b1) \
    asm("mma.sync.aligned.m16n8k16.row.col.f32.bf16.bf16.f32 " \
        "{%0,%1,%2,%3}, {%4,%5,%6,%7}, {%8,%9}, {%0,%1,%2,%3};" \
        : "+f"((acc)[0]), "+f"((acc)[1]), "+f"((acc)[2]), "+f"((acc)[3]) \
        : "r"((a).x), "r"((a).y), "r"((a).z), "r"((a).w), "r"(b0), "r"(b1))

// ---------------- prep: new_xyz + xyz transpose + clear stats (fused) ----------
__global__ void __launch_bounds__(256) k_prep0(const float* __restrict__ xyz,
                                               const int* __restrict__ perm,
                                               float* __restrict__ out) {
    int t = blockIdx.x*256 + threadIdx.x;
    if (t < 3*32*128) { ((float*)g_ps)[t] = 0.f; ((float*)g_pq)[t] = 0.f; }
    if (t < BB*NN) {        // xyz transpose (B,3,N) -> (B,N,4)
        int b = t >> 14, n = t & (NN-1);
        #pragma unroll
        for (int c = 0; c < 3; ++c)
            g_scr[OFF_XYZT + ((size_t)(b*NN + n))*4 + c] = xyz[((size_t)b*3 + c)*NN + n];
        g_scr[OFF_XYZT + ((size_t)(b*NN + n))*4 + 3] = 0.f;
    }
    if (t < BB*SS) {        // new_xyz output + query coords
        int b = t / SS, s = t % SS;
        int n = clampN(perm[s]);
        #pragma unroll
        for (int c = 0; c < 3; ++c) {
            float v = xyz[((size_t)b*3 + c)*NN + n];
            out[((size_t)b*3 + c)*SS + s] = v;
            g_scr[OFF_NXYZT + ((size_t)(b*SS + s))*4 + c] = v;
        }
        g_scr[OFF_NXYZT + ((size_t)(b*SS + s))*4 + 3] = 0.f;
    }
}

// ---------------- prep: w0 dup image + HMMA A-fragment images (hi/lo) ----------
__global__ void __launch_bounds__(256) k_prepw(const float* __restrict__ w0,
                                               const float* __restrict__ w1,
                                               const float* __restrict__ w2) {
    int t = blockIdx.x*256 + threadIdx.x;
    if (t >= 16384) return;
    if (t < 4096) {                      // gemm0 dup-pair image (w0[:, :64])
        int m = t >> 6, kk = t & 63;
        float v = w0[m*67 + kk];
        float* dst = g_scr + OFF_WD + (size_t)kk*128 + 2*m;
        dst[0] = v; dst[1] = v;
        return;
    }
    const float* W; uint32_t* base; int NW, u;
    uint32_t* wf = (uint32_t*)(g_scr + OFF_WD);
    if (t < 8192) { W = w1; NW = 4; u = t - 4096; base = wf + 16384; }
    else          { W = w2; NW = 8; u = t - 8192; base = wf + 20480; }
    int pass = u / (NW*512);
    int rest = u - pass*NW*512;
    int w = rest >> 9, ks = (rest >> 7) & 3, l = (rest >> 2) & 31, reg = rest & 3;
    int g = l >> 2, tig = l & 3;
    int m = w*16 + g + 8*(reg & 1);
    int k = ks*16 + tig*2 + 8*(reg >> 1);
    float v0 = W[m*64 + k], v1 = W[m*64 + k + 1];
    __nv_bfloat16 h0 = __float2bfloat16_rn(v0), h1 = __float2bfloat16_rn(v1);
    float f0 = __bfloat162float(h0), f1 = __bfloat162float(h1);
    base[u] = (pass == 0) ? pack2bf16(f0, f1) : pack2bf16(v0 - f0, v1 - f1);
}

// ---------------- KNN: 1 warp/query, 8 q/block; 4 candidates per ballot --------
// Distance in the shifted domain d' = |p|^2 - 2<q,p> (dropping |q|^2 preserves
// the top-32 set). One ballot per 4 candidates; neighbor index reconstructed
// arithmetically from the ballot lane (no index shuffle).
__global__ void __launch_bounds__(256) k_knn() {
    __shared__ float4 s_tile[2048];
    int tid = threadIdx.x;
    int w = tid >> 5, lane = tid & 31;
    int q = blockIdx.x*8 + w;
    const float4* xt = (const float4*)(g_scr + OFF_XYZT);
    float4 qp = ((const float4*)(g_scr + OFF_NXYZT))[q];
    float myd = INF_F; int myi = 0;
    float worst = INF_F; int wlane = 0;
    for (int tile = 0; tile < 8; ++tile) {
        __syncthreads();
        for (int i = tid; i < 2048; i += 256) {
            float4 p = xt[tile*2048 + i];
            p.w = p.x*p.x + p.y*p.y + p.z*p.z;
            s_tile[i] = p;
        }
        __syncthreads();
        for (int j = 0; j < 16; ++j) {
            float d[4];
            #pragma unroll
            for (int e = 0; e < 4; ++e) {
                float4 p = s_tile[j*128 + e*32 + lane];
                float dot = fmaf(qp.x, p.x, fmaf(qp.y, p.y, qp.z*p.z));
                d[e] = fmaf(-2.f, dot, p.w);
            }
            float dmin = fminf(fminf(d[0], d[1]), fminf(d[2], d[3]));
            unsigned hits = __ballot_sync(0xffffffffu, dmin < worst);
            while (hits) {
                int src = __ffs(hits) - 1;
                hits &= hits - 1;
                #pragma unroll
                for (int e = 0; e < 4; ++e) {
                    float dc = __shfl_sync(0xffffffffu, d[e], src);
                    if (dc < worst) {
                        int ic = tile*2048 + j*128 + e*32 + src;
                        if (lane == wlane) { myd = dc; myi = ic; }
                        float v = myd; int pos = lane;
                        #pragma unroll
                        for (int off = 16; off; off >>= 1) {
                            float ov = __shfl_xor_sync(0xffffffffu, v, off);
                            int   op = __shfl_xor_sync(0xffffffffu, pos, off);
                            if (ov > v || (ov == v && op < pos)) { v = ov; pos = op; }
                        }
                        worst = v; wlane = pos;
                    }
                }
            }
        }
    }
    g_idx[q*32 + lane] = myi;
}

// ---------------- k_gemm0: FFMA2, Y0T[b][n][64] per distinct point ----------
#define XS 132
__global__ void __launch_bounds__(128) k_gemm0(const float* __restrict__ feats) {
    float* smem = (float*)s_raw;
    float* shx = smem + 512;
    float* shw = smem + 512 + 64*XS;
    int tid = threadIdx.x;
    int tx = tid & 15, ty = tid >> 4;
    int b  = blockIdx.x >> 7;
    int n0 = (blockIdx.x & 127) * 128;
    {
        const float4* src = (const float4*)(g_scr + OFF_WD);
        float4* dst = (float4*)shw;
        #pragma unroll
        for (int i = tid; i < 2048; i += 128) dst[i] = src[i];
    }
    {
        const float* fb = feats + (size_t)b*CC*NN + n0;
        #pragma unroll
        for (int i = tid; i < 2048; i += 128) {
            int kk = i >> 5, c4 = i & 31;
            *(float4*)(shx + kk*XS + c4*4) = *(const float4*)(fb + (size_t)kk*NN + c4*4);
        }
    }
    __syncthreads();
    ull acc[8][4];
    #pragma unroll
    for (int r = 0; r < 8; ++r)
        #pragma unroll
        for (int p = 0; p < 4; ++p) acc[r][p] = 0ull;
    #pragma unroll 4
    for (int kk = 0; kk < 64; ++kk) {
        const float* xrow = shx + kk*XS + 2*tx;
        ull x0 = *(const ull*)(xrow);
        ull x1 = *(const ull*)(xrow + 32);
        ull x2 = *(const ull*)(xrow + 64);
        ull x3 = *(const ull*)(xrow + 96);
        const ulonglong2* wrow = (const ulonglong2*)(shw + kk*128 + ty*16);
        #pragma unroll
        for (int j = 0; j < 4; ++j) {
            ulonglong2 wp = wrow[j];
            FX2(acc[2*j  ][0], wp.x, x0); FX2(acc[2*j  ][1], wp.x, x1);
            FX2(acc[2*j  ][2], wp.x, x2); FX2(acc[2*j  ][3], wp.x, x3);
            FX2(acc[2*j+1][0], wp.y, x0); FX2(acc[2*j+1][1], wp.y, x1);
            FX2(acc[2*j+1][2], wp.y, x2); FX2(acc[2*j+1][3], wp.y, x3);
        }
    }
    float v[4][2][8];
    #pragma unroll
    for (int r = 0; r < 8; ++r)
        #pragma unroll
        for (int p = 0; p < 4; ++p) {
            float lo, hi; UNPK(lo, hi, acc[r][p]);
            v[p][0][r] = lo; v[p][1][r] = hi;
        }
    #pragma unroll
    for (int p = 0; p < 4; ++p)
        #pragma unroll
        for (int e = 0; e < 2; ++e) {
            int n_g = n0 + 32*p + 2*tx + e;
            float* dst = g_scr + OFF_Y0T + ((size_t)(b*NN + n_g))*64 + ty*8;
            *(float4*)dst       = make_float4(v[p][e][0], v[p][e][1], v[p][e][2], v[p][e][3]);
            *(float4*)(dst + 4) = make_float4(v[p][e][4], v[p][e][5], v[p][e][6], v[p][e][7]);
        }
}

// ---------------- k_stats1: BN0 stats over virtual Z1 ----------------
__global__ void __launch_bounds__(256) k_stats1(const float* __restrict__ w0raw) {
    int warp = blockIdx.x*8 + (threadIdx.x >> 5);
    int lane = threadIdx.x & 31;
    int m0 = 2*lane;
    float wa0 = w0raw[m0*67 + 64],     wb0 = w0raw[m0*67 + 65],     wc0 = w0raw[m0*67 + 66];
    float wa1 = w0raw[(m0+1)*67 + 64], wb1 = w0raw[(m0+1)*67 + 65], wc1 = w0raw[(m0+1)*67 + 66];
    const float4* xt = (const float4*)(g_scr + OFF_XYZT);
    const float4* nx = (const float4*)(g_scr + OFF_NXYZT);
    float s0 = 0.f, q0 = 0.f, s1 = 0.f, q1 = 0.f;
    int base = warp*128;
    float4 qc = make_float4(0,0,0,0);
    int b = 0, s = 0;
    for (int j = 0; j < 128; ++j) {
        int col = base + j;
        int G = col >> 5, k = col & 31;
        if ((j & 31) == 0) { s = G & (SS-1); b = G >> 12; qc = nx[(size_t)b*SS + s]; }
        int n = g_idx[s*32 + k];
        float4 p = xt[(size_t)b*NN + n];
        float rx = p.x - qc.x, ry = p.y - qc.y, rz = p.z - qc.z;
        float2 y = *(const float2*)(g_scr + OFF_Y0T + ((size_t)(b*NN + n))*64 + m0);
        float z0 = fmaf(wa0, rx, fmaf(wb0, ry, fmaf(wc0, rz, y.x)));
        float z1 = fmaf(wa1, rx, fmaf(wb1, ry, fmaf(wc1, rz, y.y)));
        s0 += z0; q0 = fmaf(z0, z0, q0);
        s1 += z1; q1 = fmaf(z1, z1, q1);
    }
    int bkt = warp & 31;
    atomicAdd(&g_ps[0][bkt][m0],   s0); atomicAdd(&g_pq[0][bkt][m0],   q0);
    atomicAdd(&g_ps[0][bkt][m0+1], s1); atomicAdd(&g_pq[0][bkt][m0+1], q1);
}

// ---------------- k_mma1: HMMA, Z(blob) = W1 @ relu(bn0(gather+rank3)) ----------
// smem: par f32[320]@0 | A u32[4096]@1536 | BH u32[4608]@17920 | BL@36352 (54784B)
__global__ void __launch_bounds__(128) k_mma1(const float* __restrict__ w0raw) {
    char* smem = s_raw;
    float*    sm_par = (float*)smem;
    uint32_t* Asm = (uint32_t*)(smem + 1536);
    uint32_t* BH  = (uint32_t*)(smem + 17920);
    uint32_t* BL  = (uint32_t*)(smem + 36352);
    int tid = threadIdx.x, lane = tid & 31, w = tid >> 5;
    int g = lane >> 2, tig = lane & 3;

    {   // A-fragment image (hi+lo) -> smem
        const uint4* src = (const uint4*)((const uint32_t*)(g_scr + OFF_WD) + 16384);
        uint4* dst = (uint4*)Asm;
        #pragma unroll
        for (int i = tid; i < 1024; i += 128) dst[i] = src[i];
    }
    if (tid < 64) {
        sm_par[tid]       = w0raw[tid*67 + 64];
        sm_par[64 + tid]  = w0raw[tid*67 + 65];
        sm_par[128 + tid] = w0raw[tid*67 + 66];
        sm_par[192 + tid] = g_bna[tid];
        sm_par[256 + tid] = g_bnc[tid];
    }
    __syncthreads();

    {   // B build: one thread per column; BN0+ReLU+hi/lo split, frag layout
        int col = blockIdx.x*128 + tid;
        int G = col >> 5, k = col & 31;
        int s = G & (SS-1), b = G >> 12;
        int n = g_idx[s*32 + k];
        const float4* fr = (const float4*)(g_scr + OFF_Y0T + ((size_t)(b*NN + n))*64);
        float4 p  = ((const float4*)(g_scr + OFF_XYZT))[(size_t)b*NN + n];
        float4 qc = ((const float4*)(g_scr + OFF_NXYZT))[(size_t)b*SS + s];
        float rx = p.x - qc.x, ry = p.y - qc.y, rz = p.z - qc.z;
        #pragma unroll
        for (int i = 0; i < 16; ++i) {
            float4 y = fr[i];
            float yy[4] = {y.x, y.y, y.z, y.w};
            #pragma unroll
            for (int h = 0; h < 2; ++h) {
                int m0 = 4*i + 2*h;
                float z0 = fmaf(sm_par[m0], rx, fmaf(sm_par[64+m0], ry, fmaf(sm_par[128+m0], rz, yy[2*h])));
                z0 = fmaxf(fmaf(sm_par[192+m0], z0, sm_par[256+m0]), 0.f);
                int m1 = m0 + 1;
                float z1 = fmaf(sm_par[m1], rx, fmaf(sm_par[64+m1], ry, fmaf(sm_par[128+m1], rz, yy[2*h+1])));
                z1 = fmaxf(fmaf(sm_par[192+m1], z1, sm_par[256+m1]), 0.f);
                __nv_bfloat16 h0 = __float2bfloat16_rn(z0), h1 = __float2bfloat16_rn(z1);
                float f0 = __bfloat162float(h0), f1 = __bfloat162float(h1);
                int kp = 2*i + h;
                BH[tid*36 + kp] = pack2bf16(f0, f1);
                BL[tid*36 + kp] = pack2bf16(z0 - f0, z1 - f1);
            }
        }
    }
    __syncthreads();

    float acc[16][4];
    #pragma unroll
    for (int tt = 0; tt < 16; ++tt)
        #pragma unroll
        for (int c = 0; c < 4; ++c) acc[tt][c] = 0.f;

    #pragma unroll
    for (int ks = 0; ks < 4; ++ks) {
        uint4 ah = *(const uint4*)(Asm + w*512 + ks*128 + lane*4);
        uint4 al = *(const uint4*)(Asm + 2048 + w*512 + ks*128 + lane*4);
        #pragma unroll
        for (int tt = 0; tt < 16; ++tt) {
            int ba = (tt*8 + g)*36 + ks*8 + tig;
            uint32_t b0h = BH[ba], b1h = BH[ba + 4];
            uint32_t b0l = BL[ba], b1l = BL[ba + 4];
            MMA(acc[tt], ah, b0h, b1h);
            MMA(acc[tt], al, b0h, b1h);
            MMA(acc[tt], ah, b0l, b1l);
        }
    }

    // epilogue: blob store + stats
    float4* zb = (float4*)(g_scr + OFF_Z) + (size_t)blockIdx.x*2048;
    float sg = 0.f, qg = 0.f, s8 = 0.f, q8 = 0.f;
    #pragma unroll
    for (int tt = 0; tt < 16; ++tt) {
        zb[tt*128 + w*32 + lane] = make_float4(acc[tt][0], acc[tt][1], acc[tt][2], acc[tt][3]);
        sg += acc[tt][0] + acc[tt][1];
        qg = fmaf(acc[tt][0], acc[tt][0], fmaf(acc[tt][1], acc[tt][1], qg));
        s8 += acc[tt][2] + acc[tt][3];
        q8 = fmaf(acc[tt][2], acc[tt][2], fmaf(acc[tt][3], acc[tt][3], q8));
    }
    #pragma unroll
    for (int o = 2; o; o >>= 1) {
        sg += __shfl_down_sync(0xffffffffu, sg, o, 4);
        qg += __shfl_down_sync(0xffffffffu, qg, o, 4);
        s8 += __shfl_down_sync(0xffffffffu, s8, o, 4);
        q8 += __shfl_down_sync(0xffffffffu, q8, o, 4);
    }
    if (tig == 0) {
        int bkt = blockIdx.x & 31;
        int m = w*16 + g;
        atomicAdd(&g_ps[1][bkt][m],     sg); atomicAdd(&g_pq[1][bkt][m],     qg);
        atomicAdd(&g_ps[1][bkt][m + 8], s8); atomicAdd(&g_pq[1][bkt][m + 8], q8);
    }
}

// ---------------- k_mma2: HMMA, maxpool(relu(bn2(W2 @ relu(bn1(Zblob))))) ------
// smem: bna[64]@0 bnc[64]@256 | A u32[8192]@512 | BH@33280 | BL@51712 (70144B)
__global__ void __launch_bounds__(256) k_mma2() {
    char* smem = s_raw;
    float*    bna = (float*)smem;
    float*    bnc = (float*)(smem + 256);
    uint32_t* Asm = (uint32_t*)(smem + 512);
    uint32_t* BH  = (uint32_t*)(smem + 33280);
    uint32_t* BL  = (uint32_t*)(smem + 51712);
    int tid = threadIdx.x, lane = tid & 31, w = tid >> 5;
    int g = lane >> 2, tig = lane & 3;

    {
        const uint4* src = (const uint4*)((const uint32_t*)(g_scr + OFF_WD) + 20480);
        uint4* dst = (uint4*)Asm;
        #pragma unroll
        for (int i = tid; i < 2048; i += 256) dst[i] = src[i];
    }
    if (tid < 64) { bna[tid] = g_bna[128 + tid]; bnc[tid] = g_bnc[128 + tid]; }
    __syncthreads();

    {   // prologue: decode blob -> BN1/ReLU -> hi/lo B fragments
        const float* zb = g_scr + OFF_Z + (size_t)blockIdx.x*8192;
        #pragma unroll
        for (int j = 0; j < 16; ++j) {
            int p = j*256 + tid;
            int ptig = p & 3, c = (p >> 2) & 3, gh = (p >> 4) & 3;
            int w1 = (p >> 6) & 3, tt = p >> 8;
            int i0 = tt*512 + w1*128 + gh*32 + ptig*4 + c;
            float z0 = zb[i0], z1 = zb[i0 + 16];
            int kch = w1*16 + 2*gh + 8*(c >> 1);
            z0 = fmaxf(fmaf(bna[kch],     z0, bnc[kch]),     0.f);
            z1 = fmaxf(fmaf(bna[kch + 1], z1, bnc[kch + 1]), 0.f);
            __nv_bfloat16 h0 = __float2bfloat16_rn(z0), h1 = __float2bfloat16_rn(z1);
            float f0 = __bfloat162float(h0), f1 = __bfloat162float(h1);
            int col = tt*8 + ptig*2 + (c & 1);
            int kp  = w1*8 + gh + 4*(c >> 1);
            BH[col*36 + kp] = pack2bf16(f0, f1);
            BL[col*36 + kp] = pack2bf16(z0 - f0, z1 - f1);
        }
    }
    __syncthreads();

    float acc[16][4];
    #pragma unroll
    for (int tt = 0; tt < 16; ++tt)
        #pragma unroll
        for (int c = 0; c < 4; ++c) acc[tt][c] = 0.f;

    #pragma unroll
    for (int ks = 0; ks < 4; ++ks) {
        uint4 ah = *(const uint4*)(Asm + w*512 + ks*128 + lane*4);
        uint4 al = *(const uint4*)(Asm + 4096 + w*512 + ks*128 + lane*4);
        #pragma unroll
        for (int tt = 0; tt < 16; ++tt) {
            int ba = (tt*8 + g)*36 + ks*8 + tig;
            uint32_t b0h = BH[ba], b1h = BH[ba + 4];
            uint32_t b0l = BL[ba], b1l = BL[ba + 4];
            MMA(acc[tt], ah, b0h, b1h);
            MMA(acc[tt], al, b0h, b1h);
            MMA(acc[tt], ah, b0l, b1l);
        }
    }

    // epilogue: per-32-col max/min pools + stats
    float2* mm = (float2*)(g_scr + OFF_MM);
    float sg = 0.f, qg = 0.f, s8 = 0.f, q8 = 0.f;
    #pragma unroll
    for (int p = 0; p < 4; ++p) {
        float mxg = -INF_F, mng = INF_F, mx8 = -INF_F, mn8 = INF_F;
        #pragma unroll
        for (int t4 = 0; t4 < 4; ++t4) {
            int tt = p*4 + t4;
            mxg = fmaxf(mxg, fmaxf(acc[tt][0], acc[tt][1]));
            mng = fminf(mng, fminf(acc[tt][0], acc[tt][1]));
            mx8 = fmaxf(mx8, fmaxf(acc[tt][2], acc[tt][3]));
            mn8 = fminf(mn8, fminf(acc[tt][2], acc[tt][3]));
            sg += acc[tt][0] + acc[tt][1];
            qg = fmaf(acc[tt][0], acc[tt][0], fmaf(acc[tt][1], acc[tt][1], qg));
            s8 += acc[tt][2] + acc[tt][3];
            q8 = fmaf(acc[tt][2], acc[tt][2], fmaf(acc[tt][3], acc[tt][3], q8));
        }
        #pragma unroll
        for (int o = 2; o; o >>= 1) {
            mxg = fmaxf(mxg, __shfl_down_sync(0xffffffffu, mxg, o, 4));
            mng = fminf(mng, __shfl_down_sync(0xffffffffu, mng, o, 4));
            mx8 = fmaxf(mx8, __shfl_down_sync(0xffffffffu, mx8, o, 4));
            mn8 = fminf(mn8, __shfl_down_sync(0xffffffffu, mn8, o, 4));
        }
        if (tig == 0) {
            int m = w*16 + g;
            mm[(size_t)m*NGRP + blockIdx.x*4 + p]       = make_float2(mxg, mng);
            mm[(size_t)(m + 8)*NGRP + blockIdx.x*4 + p] = make_float2(mx8, mn8);
        }
    }
    #pragma unroll
    for (int o = 2; o; o >>= 1) {
        sg += __shfl_down_sync(0xffffffffu, sg, o, 4);
        qg += __shfl_down_sync(0xffffffffu, qg, o, 4);
        s8 += __shfl_down_sync(0xffffffffu, s8, o, 4);
        q8 += __shfl_down_sync(0xffffffffu, q8, o, 4);
    }
    if (tig == 0) {
        int bkt = blockIdx.x & 31;
        int m = w*16 + g;
        atomicAdd(&g_ps[2][bkt][m],     sg); atomicAdd(&g_pq[2][bkt][m],     qg);
        atomicAdd(&g_ps[2][bkt][m + 8], s8); atomicAdd(&g_pq[2][bkt][m + 8], q8);
    }
}

// ---------------- BN affine params ----------------
__global__ void k_bnparam(int slot, const float* __restrict__ g,
                          const float* __restrict__ b, int M) {
    int m = threadIdx.x;
    if (m >= M) return;
    float s = 0.f, q = 0.f;
    #pragma unroll
    for (int j = 0; j < 32; ++j) { s += g_ps[slot][j][m]; q += g_pq[slot][j][m]; }
    const float cnt = (float)NCOL;
    float mu  = s / cnt;
    float var = q / cnt - mu*mu;
    float a = g[m] * rsqrtf(var + BN_EPS);
    g_bna[slot*128 + m] = a;
    g_bnc[slot*128 + m] = b[m] - mu*a;
}

// ---------------- finalize ----------------
__global__ void __launch_bounds__(256) k_final(float* __restrict__ out) {
    int t = blockIdx.x*256 + threadIdx.x;
    if (t >= BB*128*SS) return;
    int s  = t & (SS-1);
    int bc = t >> 12;
    int c = bc & 127, b = bc >> 7;
    float a  = g_bna[2*128 + c];
    float cc = g_bnc[2*128 + c];
    const float2* mm = (const float2*)(g_scr + OFF_MM);
    float2 e = mm[(size_t)c*NGRP + b*SS + s];
    float z = (a >= 0.f) ? e.x : e.y;
    out[BB*3*SS + t] = fmaxf(fmaf(a, z, cc), 0.f);
}

// ---------------- launch (single stream, round-10 structure) ----------------
extern "C" void kernel_launch(void* const* d_in, const int* in_sizes, int n_in,
                              void* d_out, int out_size) {
    (void)in_sizes; (void)n_in; (void)out_size;
    const float* xyz   = (const float*)d_in[0];
    const float* feats = (const float*)d_in[1];
    const int*   perm  = (const int*)d_in[2];
    const float* w0 = (const float*)d_in[3];
    const float* g0 = (const float*)d_in[4];
    const float* b0 = (const float*)d_in[5];
    const float* w1 = (const float*)d_in[6];
    const float* g1 = (const float*)d_in[7];
    const float* b1 = (const float*)d_in[8];
    const float* w2 = (const float*)d_in[9];
    const float* g2 = (const float*)d_in[10];
    const float* b2 = (const float*)d_in[11];
    float* out = (float*)d_out;

    const int sm0  = (512 + 64*XS + 64*128) * 4;   // 68608 (gemm0)
    const int smm1 = 54784;
    const int smm2 = 70144;
    cudaFuncSetAttribute(k_gemm0, cudaFuncAttributeMaxDynamicSharedMemorySize, sm0);
    cudaFuncSetAttribute(k_mma1,  cudaFuncAttributeMaxDynamicSharedMemorySize, smm1);
    cudaFuncSetAttribute(k_mma2,  cudaFuncAttributeMaxDynamicSharedMemorySize, smm2);

    k_prep0 <<<(BB*NN)/256, 256>>>(xyz, perm, out);
    k_prepw <<<64, 256>>>(w0, w1, w2);
    k_knn   <<<SS/8, 256>>>();
    k_gemm0 <<<BB*NN/128, 128, sm0>>>(feats);
    k_stats1<<<NCOL/1024, 256>>>(w0);
    k_bnparam<<<1,128>>>(0, g0, b0, 64);
    k_mma1  <<<NCOL/128, 128, smm1>>>(w0);
    k_bnparam<<<1,128>>>(1, g1, b1, 64);
    k_mma2  <<<NCOL/128, 256, smm2>>>();
    k_bnparam<<<1,128>>>(2, g2, b2, 128);
    k_final<<<(BB*128*SS)/256, 256>>>(out);
}

// round 17
// speedup vs baseline: 1.1141x; 1.0049x over previous
#include <cuda_runtime.h>
#include <cuda_bf16.h>
#include <math.h>
#include <stdint.h>

// ---------------- problem constants ----------------
#define BB 8
#define NN 16384
#define SS 4096
#define KK 32
#define CC 64
#define NCOL (BB*SS*KK)          // 1048576 columns
#define NGRP (NCOL/32)           // 32768 (b,s) groups
#define BN_EPS 1e-5f
#define INF_F 3.0e38f

// ---------------- scratch layout (floats) ----------------
#define OFF_Y0T     ((size_t)0)           // (B,N,64)
#define OFF_XYZT    ((size_t)8388608)     // (B,N,4)
#define OFF_NXYZT   ((size_t)8912896)     // (B,S,4)
#define OFF_Z       ((size_t)9043968)     // fragment-blob Z: 8192 blocks x 8192 f32
#define OFF_MM      ((size_t)76152832)    // 128 x NGRP float2
#define OFF_WD      ((size_t)84541440)    // w0 dup image + HMMA A-fragment images
#define SCR_TOTAL   ((size_t)84590592)

__device__ float g_scr[SCR_TOTAL];
__device__ int   g_idx[SS*KK];
__device__ float g_ps[3][32][128];
__device__ float g_pq[3][32][128];
__device__ float g_bna[3*128];
__device__ float g_bnc[3*128];

// single shared symbol; kernels cast locally
extern __shared__ char s_raw[];

static __device__ __forceinline__ int clampN(int n) {
    return n < 0 ? 0 : (n >= NN ? NN-1 : n);
}

typedef unsigned long long ull;
#define FX2(acc, w, x) \
    asm("fma.rn.f32x2 %0, %1, %2, %0;" : "+l"(acc) : "l"(w), "l"(x))
#define UNPK(lo, hi, p) \
    asm("mov.b64 {%0, %1}, %2;" : "=f"(lo), "=f"(hi) : "l"(p))

__device__ __forceinline__ uint32_t pack2bf16(float a, float b) {
    __nv_bfloat162 h = __floats2bfloat162_rn(a, b);
    return *(uint32_t*)&h;
}

// HMMA m16n8k16 bf16 -> f32
#define MMA(acc, a, b0, b1) \
    asm("mma.sync.aligned.m16n8k16.row.col.f32.bf16.bf16.f32 " \
        "{%0,%1,%2,%3}, {%4,%5,%6,%7}, {%8,%9}, {%0,%1,%2,%3};" \
        : "+f"((acc)[0]), "+f"((acc)[1]), "+f"((acc)[2]), "+f"((acc)[3]) \
        : "r"((a).x), "r"((a).y), "r"((a).z), "r"((a).w), "r"(b0), "r"(b1))

// ---------------- prep: new_xyz + xyz transpose + clear stats (fused) ----------
__global__ void __launch_bounds__(256) k_prep0(const float* __restrict__ xyz,
                                               const int* __restrict__ perm,
                                               float* __restrict__ out) {
    int t = blockIdx.x*256 + threadIdx.x;
    if (t < 3*32*128) { ((float*)g_ps)[t] = 0.f; ((float*)g_pq)[t] = 0.f; }
    if (t < BB*NN) {        // xyz transpose (B,3,N) -> (B,N,4)
        int b = t >> 14, n = t & (NN-1);
        #pragma unroll
        for (int c = 0; c < 3; ++c)
            g_scr[OFF_XYZT + ((size_t)(b*NN + n))*4 + c] = xyz[((size_t)b*3 + c)*NN + n];
        g_scr[OFF_XYZT + ((size_t)(b*NN + n))*4 + 3] = 0.f;
    }
    if (t < BB*SS) {        // new_xyz output + query coords
        int b = t / SS, s = t % SS;
        int n = clampN(perm[s]);
        #pragma unroll
        for (int c = 0; c < 3; ++c) {
            float v = xyz[((size_t)b*3 + c)*NN + n];
            out[((size_t)b*3 + c)*SS + s] = v;
            g_scr[OFF_NXYZT + ((size_t)(b*SS + s))*4 + c] = v;
        }
        g_scr[OFF_NXYZT + ((size_t)(b*SS + s))*4 + 3] = 0.f;
    }
}

// ---------------- prep: w0 dup image + HMMA A-fragment images (hi/lo) ----------
__global__ void __launch_bounds__(256) k_prepw(const float* __restrict__ w0,
                                               const float* __restrict__ w1,
                                               const float* __restrict__ w2) {
    int t = blockIdx.x*256 + threadIdx.x;
    if (t >= 16384) return;
    if (t < 4096) {                      // gemm0 dup-pair image (w0[:, :64])
        int m = t >> 6, kk = t & 63;
        float v = w0[m*67 + kk];
        float* dst = g_scr + OFF_WD + (size_t)kk*128 + 2*m;
        dst[0] = v; dst[1] = v;
        return;
    }
    const float* W; uint32_t* base; int NW, u;
    uint32_t* wf = (uint32_t*)(g_scr + OFF_WD);
    if (t < 8192) { W = w1; NW = 4; u = t - 4096; base = wf + 16384; }
    else          { W = w2; NW = 8; u = t - 8192; base = wf + 20480; }
    int pass = u / (NW*512);
    int rest = u - pass*NW*512;
    int w = rest >> 9, ks = (rest >> 7) & 3, l = (rest >> 2) & 31, reg = rest & 3;
    int g = l >> 2, tig = l & 3;
    int m = w*16 + g + 8*(reg & 1);
    int k = ks*16 + tig*2 + 8*(reg >> 1);
    float v0 = W[m*64 + k], v1 = W[m*64 + k + 1];
    __nv_bfloat16 h0 = __float2bfloat16_rn(v0), h1 = __float2bfloat16_rn(v1);
    float f0 = __bfloat162float(h0), f1 = __bfloat162float(h1);
    base[u] = (pass == 0) ? pack2bf16(f0, f1) : pack2bf16(v0 - f0, v1 - f1);
}

// ---------------- KNN: 1 warp/query, 8 q/block; 4 candidates per ballot --------
// Query premultiplied by -2 so each candidate distance is exactly 3 FMAs:
// d' = fmaf(qx,px, fmaf(qy,py, fmaf(qz,pz, |p|^2))) with (qx,qy,qz) = -2*query.
__global__ void __launch_bounds__(256) k_knn() {
    __shared__ float4 s_tile[2048];
    int tid = threadIdx.x;
    int w = tid >> 5, lane = tid & 31;
    int q = blockIdx.x*8 + w;
    const float4* xt = (const float4*)(g_scr + OFF_XYZT);
    float4 qp = ((const float4*)(g_scr + OFF_NXYZT))[q];
    qp.x *= -2.f; qp.y *= -2.f; qp.z *= -2.f;
    float myd = INF_F; int myi = 0;
    float worst = INF_F; int wlane = 0;
    for (int tile = 0; tile < 8; ++tile) {
        __syncthreads();
        for (int i = tid; i < 2048; i += 256) {
            float4 p = xt[tile*2048 + i];
            p.w = p.x*p.x + p.y*p.y + p.z*p.z;
            s_tile[i] = p;
        }
        __syncthreads();
        for (int j = 0; j < 16; ++j) {
            float d[4];
            #pragma unroll
            for (int e = 0; e < 4; ++e) {
                float4 p = s_tile[j*128 + e*32 + lane];
                d[e] = fmaf(qp.x, p.x, fmaf(qp.y, p.y, fmaf(qp.z, p.z, p.w)));
            }
            float dmin = fminf(fminf(d[0], d[1]), fminf(d[2], d[3]));
            unsigned hits = __ballot_sync(0xffffffffu, dmin < worst);
            while (hits) {
                int src = __ffs(hits) - 1;
                hits &= hits - 1;
                #pragma unroll
                for (int e = 0; e < 4; ++e) {
                    float dc = __shfl_sync(0xffffffffu, d[e], src);
                    if (dc < worst) {
                        int ic = tile*2048 + j*128 + e*32 + src;
                        if (lane == wlane) { myd = dc; myi = ic; }
                        float v = myd; int pos = lane;
                        #pragma unroll
                        for (int off = 16; off; off >>= 1) {
                            float ov = __shfl_xor_sync(0xffffffffu, v, off);
                            int   op = __shfl_xor_sync(0xffffffffu, pos, off);
                            if (ov > v || (ov == v && op < pos)) { v = ov; pos = op; }
                        }
                        worst = v; wlane = pos;
                    }
                }
            }
        }
    }
    g_idx[q*32 + lane] = myi;
}

// ---------------- k_gemm0: FFMA2, Y0T[b][n][64] per distinct point ----------
#define XS 132
__global__ void __launch_bounds__(128) k_gemm0(const float* __restrict__ feats) {
    float* smem = (float*)s_raw;
    float* shx = smem + 512;
    float* shw = smem + 512 + 64*XS;
    int tid = threadIdx.x;
    int tx = tid & 15, ty = tid >> 4;
    int b  = blockIdx.x >> 7;
    int n0 = (blockIdx.x & 127) * 128;
    {
        const float4* src = (const float4*)(g_scr + OFF_WD);
        float4* dst = (float4*)shw;
        #pragma unroll
        for (int i = tid; i < 2048; i += 128) dst[i] = src[i];
    }
    {
        const float* fb = feats + (size_t)b*CC*NN + n0;
        #pragma unroll
        for (int i = tid; i < 2048; i += 128) {
            int kk = i >> 5, c4 = i & 31;
            *(float4*)(shx + kk*XS + c4*4) = *(const float4*)(fb + (size_t)kk*NN + c4*4);
        }
    }
    __syncthreads();
    ull acc[8][4];
    #pragma unroll
    for (int r = 0; r < 8; ++r)
        #pragma unroll
        for (int p = 0; p < 4; ++p) acc[r][p] = 0ull;
    #pragma unroll 4
    for (int kk = 0; kk < 64; ++kk) {
        const float* xrow = shx + kk*XS + 2*tx;
        ull x0 = *(const ull*)(xrow);
        ull x1 = *(const ull*)(xrow + 32);
        ull x2 = *(const ull*)(xrow + 64);
        ull x3 = *(const ull*)(xrow + 96);
        const ulonglong2* wrow = (const ulonglong2*)(shw + kk*128 + ty*16);
        #pragma unroll
        for (int j = 0; j < 4; ++j) {
            ulonglong2 wp = wrow[j];
            FX2(acc[2*j  ][0], wp.x, x0); FX2(acc[2*j  ][1], wp.x, x1);
            FX2(acc[2*j  ][2], wp.x, x2); FX2(acc[2*j  ][3], wp.x, x3);
            FX2(acc[2*j+1][0], wp.y, x0); FX2(acc[2*j+1][1], wp.y, x1);
            FX2(acc[2*j+1][2], wp.y, x2); FX2(acc[2*j+1][3], wp.y, x3);
        }
    }
    float v[4][2][8];
    #pragma unroll
    for (int r = 0; r < 8; ++r)
        #pragma unroll
        for (int p = 0; p < 4; ++p) {
            float lo, hi; UNPK(lo, hi, acc[r][p]);
            v[p][0][r] = lo; v[p][1][r] = hi;
        }
    #pragma unroll
    for (int p = 0; p < 4; ++p)
        #pragma unroll
        for (int e = 0; e < 2; ++e) {
            int n_g = n0 + 32*p + 2*tx + e;
            float* dst = g_scr + OFF_Y0T + ((size_t)(b*NN + n_g))*64 + ty*8;
            *(float4*)dst       = make_float4(v[p][e][0], v[p][e][1], v[p][e][2], v[p][e][3]);
            *(float4*)(dst + 4) = make_float4(v[p][e][4], v[p][e][5], v[p][e][6], v[p][e][7]);
        }
}

// ---------------- k_stats1: BN0 stats over virtual Z1 ----------------
__global__ void __launch_bounds__(256) k_stats1(const float* __restrict__ w0raw) {
    int warp = blockIdx.x*8 + (threadIdx.x >> 5);
    int lane = threadIdx.x & 31;
    int m0 = 2*lane;
    float wa0 = w0raw[m0*67 + 64],     wb0 = w0raw[m0*67 + 65],     wc0 = w0raw[m0*67 + 66];
    float wa1 = w0raw[(m0+1)*67 + 64], wb1 = w0raw[(m0+1)*67 + 65], wc1 = w0raw[(m0+1)*67 + 66];
    const float4* xt = (const float4*)(g_scr + OFF_XYZT);
    const float4* nx = (const float4*)(g_scr + OFF_NXYZT);
    float s0 = 0.f, q0 = 0.f, s1 = 0.f, q1 = 0.f;
    int base = warp*128;
    float4 qc = make_float4(0,0,0,0);
    int b = 0, s = 0;
    for (int j = 0; j < 128; ++j) {
        int col = base + j;
        int G = col >> 5, k = col & 31;
        if ((j & 31) == 0) { s = G & (SS-1); b = G >> 12; qc = nx[(size_t)b*SS + s]; }
        int n = g_idx[s*32 + k];
        float4 p = xt[(size_t)b*NN + n];
        float rx = p.x - qc.x, ry = p.y - qc.y, rz = p.z - qc.z;
        float2 y = *(const float2*)(g_scr + OFF_Y0T + ((size_t)(b*NN + n))*64 + m0);
        float z0 = fmaf(wa0, rx, fmaf(wb0, ry, fmaf(wc0, rz, y.x)));
        float z1 = fmaf(wa1, rx, fmaf(wb1, ry, fmaf(wc1, rz, y.y)));
        s0 += z0; q0 = fmaf(z0, z0, q0);
        s1 += z1; q1 = fmaf(z1, z1, q1);
    }
    int bkt = warp & 31;
    atomicAdd(&g_ps[0][bkt][m0],   s0); atomicAdd(&g_pq[0][bkt][m0],   q0);
    atomicAdd(&g_ps[0][bkt][m0+1], s1); atomicAdd(&g_pq[0][bkt][m0+1], q1);
}

// ---------------- k_mma1: HMMA, Z(blob) = W1 @ relu(bn0(gather+rank3)) ----------
// smem: par f32[320]@0 | A u32[4096]@1536 | BH u32[4608]@17920 | BL@36352 (54784B)
__global__ void __launch_bounds__(128) k_mma1(const float* __restrict__ w0raw) {
    char* smem = s_raw;
    float*    sm_par = (float*)smem;
    uint32_t* Asm = (uint32_t*)(smem + 1536);
    uint32_t* BH  = (uint32_t*)(smem + 17920);
    uint32_t* BL  = (uint32_t*)(smem + 36352);
    int tid = threadIdx.x, lane = tid & 31, w = tid >> 5;
    int g = lane >> 2, tig = lane & 3;

    {   // A-fragment image (hi+lo) -> smem
        const uint4* src = (const uint4*)((const uint32_t*)(g_scr + OFF_WD) + 16384);
        uint4* dst = (uint4*)Asm;
        #pragma unroll
        for (int i = tid; i < 1024; i += 128) dst[i] = src[i];
    }
    if (tid < 64) {
        sm_par[tid]       = w0raw[tid*67 + 64];
        sm_par[64 + tid]  = w0raw[tid*67 + 65];
        sm_par[128 + tid] = w0raw[tid*67 + 66];
        sm_par[192 + tid] = g_bna[tid];
        sm_par[256 + tid] = g_bnc[tid];
    }
    __syncthreads();

    {   // B build: one thread per column; BN0+ReLU+hi/lo split, frag layout
        int col = blockIdx.x*128 + tid;
        int G = col >> 5, k = col & 31;
        int s = G & (SS-1), b = G >> 12;
        int n = g_idx[s*32 + k];
        const float4* fr = (const float4*)(g_scr + OFF_Y0T + ((size_t)(b*NN + n))*64);
        float4 p  = ((const float4*)(g_scr + OFF_XYZT))[(size_t)b*NN + n];
        float4 qc = ((const float4*)(g_scr + OFF_NXYZT))[(size_t)b*SS + s];
        float rx = p.x - qc.x, ry = p.y - qc.y, rz = p.z - qc.z;
        #pragma unroll
        for (int i = 0; i < 16; ++i) {
            float4 y = fr[i];
            float yy[4] = {y.x, y.y, y.z, y.w};
            #pragma unroll
            for (int h = 0; h < 2; ++h) {
                int m0 = 4*i + 2*h;
                float z0 = fmaf(sm_par[m0], rx, fmaf(sm_par[64+m0], ry, fmaf(sm_par[128+m0], rz, yy[2*h])));
                z0 = fmaxf(fmaf(sm_par[192+m0], z0, sm_par[256+m0]), 0.f);
                int m1 = m0 + 1;
                float z1 = fmaf(sm_par[m1], rx, fmaf(sm_par[64+m1], ry, fmaf(sm_par[128+m1], rz, yy[2*h+1])));
                z1 = fmaxf(fmaf(sm_par[192+m1], z1, sm_par[256+m1]), 0.f);
                __nv_bfloat16 h0 = __float2bfloat16_rn(z0), h1 = __float2bfloat16_rn(z1);
                float f0 = __bfloat162float(h0), f1 = __bfloat162float(h1);
                int kp = 2*i + h;
                BH[tid*36 + kp] = pack2bf16(f0, f1);
                BL[tid*36 + kp] = pack2bf16(z0 - f0, z1 - f1);
            }
        }
    }
    __syncthreads();

    float acc[16][4];
    #pragma unroll
    for (int tt = 0; tt < 16; ++tt)
        #pragma unroll
        for (int c = 0; c < 4; ++c) acc[tt][c] = 0.f;

    #pragma unroll
    for (int ks = 0; ks < 4; ++ks) {
        uint4 ah = *(const uint4*)(Asm + w*512 + ks*128 + lane*4);
        uint4 al = *(const uint4*)(Asm + 2048 + w*512 + ks*128 + lane*4);
        #pragma unroll
        for (int tt = 0; tt < 16; ++tt) {
            int ba = (tt*8 + g)*36 + ks*8 + tig;
            uint32_t b0h = BH[ba], b1h = BH[ba + 4];
            uint32_t b0l = BL[ba], b1l = BL[ba + 4];
            MMA(acc[tt], ah, b0h, b1h);
            MMA(acc[tt], al, b0h, b1h);
            MMA(acc[tt], ah, b0l, b1l);
        }
    }

    // epilogue: blob store + stats
    float4* zb = (float4*)(g_scr + OFF_Z) + (size_t)blockIdx.x*2048;
    float sg = 0.f, qg = 0.f, s8 = 0.f, q8 = 0.f;
    #pragma unroll
    for (int tt = 0; tt < 16; ++tt) {
        zb[tt*128 + w*32 + lane] = make_float4(acc[tt][0], acc[tt][1], acc[tt][2], acc[tt][3]);
        sg += acc[tt][0] + acc[tt][1];
        qg = fmaf(acc[tt][0], acc[tt][0], fmaf(acc[tt][1], acc[tt][1], qg));
        s8 += acc[tt][2] + acc[tt][3];
        q8 = fmaf(acc[tt][2], acc[tt][2], fmaf(acc[tt][3], acc[tt][3], q8));
    }
    #pragma unroll
    for (int o = 2; o; o >>= 1) {
        sg += __shfl_down_sync(0xffffffffu, sg, o, 4);
        qg += __shfl_down_sync(0xffffffffu, qg, o, 4);
        s8 += __shfl_down_sync(0xffffffffu, s8, o, 4);
        q8 += __shfl_down_sync(0xffffffffu, q8, o, 4);
    }
    if (tig == 0) {
        int bkt = blockIdx.x & 31;
        int m = w*16 + g;
        atomicAdd(&g_ps[1][bkt][m],     sg); atomicAdd(&g_pq[1][bkt][m],     qg);
        atomicAdd(&g_ps[1][bkt][m + 8], s8); atomicAdd(&g_pq[1][bkt][m + 8], q8);
    }
}

// ---------------- k_mma2: HMMA, maxpool(relu(bn2(W2 @ relu(bn1(Zblob))))) ------
// Processes blob blocks in REVERSE order: mma1 wrote the blob front-to-back, so
// the tail is L2-resident when mma2 starts; reading tail-first converts the
// first waves' blob reads into L2 hits.
// smem: bna[64]@0 bnc[64]@256 | A u32[8192]@512 | BH@33280 | BL@51712 (70144B)
__global__ void __launch_bounds__(256) k_mma2() {
    char* smem = s_raw;
    float*    bna = (float*)smem;
    float*    bnc = (float*)(smem + 256);
    uint32_t* Asm = (uint32_t*)(smem + 512);
    uint32_t* BH  = (uint32_t*)(smem + 33280);
    uint32_t* BL  = (uint32_t*)(smem + 51712);
    int tid = threadIdx.x, lane = tid & 31, w = tid >> 5;
    int g = lane >> 2, tig = lane & 3;
    int rb = (NCOL/128 - 1) - blockIdx.x;      // reversed logical block id

    {
        const uint4* src = (const uint4*)((const uint32_t*)(g_scr + OFF_WD) + 20480);
        uint4* dst = (uint4*)Asm;
        #pragma unroll
        for (int i = tid; i < 2048; i += 256) dst[i] = src[i];
    }
    if (tid < 64) { bna[tid] = g_bna[128 + tid]; bnc[tid] = g_bnc[128 + tid]; }
    __syncthreads();

    {   // prologue: decode blob -> BN1/ReLU -> hi/lo B fragments
        const float* zb = g_scr + OFF_Z + (size_t)rb*8192;
        #pragma unroll
        for (int j = 0; j < 16; ++j) {
            int p = j*256 + tid;
            int ptig = p & 3, c = (p >> 2) & 3, gh = (p >> 4) & 3;
            int w1 = (p >> 6) & 3, tt = p >> 8;
            int i0 = tt*512 + w1*128 + gh*32 + ptig*4 + c;
            float z0 = zb[i0], z1 = zb[i0 + 16];
            int kch = w1*16 + 2*gh + 8*(c >> 1);
            z0 = fmaxf(fmaf(bna[kch],     z0, bnc[kch]),     0.f);
            z1 = fmaxf(fmaf(bna[kch + 1], z1, bnc[kch + 1]), 0.f);
            __nv_bfloat16 h0 = __float2bfloat16_rn(z0), h1 = __float2bfloat16_rn(z1);
            float f0 = __bfloat162float(h0), f1 = __bfloat162float(h1);
            int col = tt*8 + ptig*2 + (c & 1);
            int kp  = w1*8 + gh + 4*(c >> 1);
            BH[col*36 + kp] = pack2bf16(f0, f1);
            BL[col*36 + kp] = pack2bf16(z0 - f0, z1 - f1);
        }
    }
    __syncthreads();

    float acc[16][4];
    #pragma unroll
    for (int tt = 0; tt < 16; ++tt)
        #pragma unroll
        for (int c = 0; c < 4; ++c) acc[tt][c] = 0.f;

    #pragma unroll
    for (int ks = 0; ks < 4; ++ks) {
        uint4 ah = *(const uint4*)(Asm + w*512 + ks*128 + lane*4);
        uint4 al = *(const uint4*)(Asm + 4096 + w*512 + ks*128 + lane*4);
        #pragma unroll
        for (int tt = 0; tt < 16; ++tt) {
            int ba = (tt*8 + g)*36 + ks*8 + tig;
            uint32_t b0h = BH[ba], b1h = BH[ba + 4];
            uint32_t b0l = BL[ba], b1l = BL[ba + 4];
            MMA(acc[tt], ah, b0h, b1h);
            MMA(acc[tt], al, b0h, b1h);
            MMA(acc[tt], ah, b0l, b1l);
        }
    }

    // epilogue: per-32-col max/min pools + stats
    float2* mm = (float2*)(g_scr + OFF_MM);
    float sg = 0.f, qg = 0.f, s8 = 0.f, q8 = 0.f;
    #pragma unroll
    for (int p = 0; p < 4; ++p) {
        float mxg = -INF_F, mng = INF_F, mx8 = -INF_F, mn8 = INF_F;
        #pragma unroll
        for (int t4 = 0; t4 < 4; ++t4) {
            int tt = p*4 + t4;
            mxg = fmaxf(mxg, fmaxf(acc[tt][0], acc[tt][1]));
            mng = fminf(mng, fminf(acc[tt][0], acc[tt][1]));
            mx8 = fmaxf(mx8, fmaxf(acc[tt][2], acc[tt][3]));
            mn8 = fminf(mn8, fminf(acc[tt][2], acc[tt][3]));
            sg += acc[tt][0] + acc[tt][1];
            qg = fmaf(acc[tt][0], acc[tt][0], fmaf(acc[tt][1], acc[tt][1], qg));
            s8 += acc[tt][2] + acc[tt][3];
            q8 = fmaf(acc[tt][2], acc[tt][2], fmaf(acc[tt][3], acc[tt][3], q8));
        }
        #pragma unroll
        for (int o = 2; o; o >>= 1) {
            mxg = fmaxf(mxg, __shfl_down_sync(0xffffffffu, mxg, o, 4));
            mng = fminf(mng, __shfl_down_sync(0xffffffffu, mng, o, 4));
            mx8 = fmaxf(mx8, __shfl_down_sync(0xffffffffu, mx8, o, 4));
            mn8 = fminf(mn8, __shfl_down_sync(0xffffffffu, mn8, o, 4));
        }
        if (tig == 0) {
            int m = w*16 + g;
            mm[(size_t)m*NGRP + rb*4 + p]       = make_float2(mxg, mng);
            mm[(size_t)(m + 8)*NGRP + rb*4 + p] = make_float2(mx8, mn8);
        }
    }
    #pragma unroll
    for (int o = 2; o; o >>= 1) {
        sg += __shfl_down_sync(0xffffffffu, sg, o, 4);
        qg += __shfl_down_sync(0xffffffffu, qg, o, 4);
        s8 += __shfl_down_sync(0xffffffffu, s8, o, 4);
        q8 += __shfl_down_sync(0xffffffffu, q8, o, 4);
    }
    if (tig == 0) {
        int bkt = rb & 31;
        int m = w*16 + g;
        atomicAdd(&g_ps[2][bkt][m],     sg); atomicAdd(&g_pq[2][bkt][m],     qg);
        atomicAdd(&g_ps[2][bkt][m + 8], s8); atomicAdd(&g_pq[2][bkt][m + 8], q8);
    }
}

// ---------------- BN affine params ----------------
__global__ void k_bnparam(int slot, const float* __restrict__ g,
                          const float* __restrict__ b, int M) {
    int m = threadIdx.x;
    if (m >= M) return;
    float s = 0.f, q = 0.f;
    #pragma unroll
    for (int j = 0; j < 32; ++j) { s += g_ps[slot][j][m]; q += g_pq[slot][j][m]; }
    const float cnt = (float)NCOL;
    float mu  = s / cnt;
    float var = q / cnt - mu*mu;
    float a = g[m] * rsqrtf(var + BN_EPS);
    g_bna[slot*128 + m] = a;
    g_bnc[slot*128 + m] = b[m] - mu*a;
}

// ---------------- finalize ----------------
__global__ void __launch_bounds__(256) k_final(float* __restrict__ out) {
    int t = blockIdx.x*256 + threadIdx.x;
    if (t >= BB*128*SS) return;
    int s  = t & (SS-1);
    int bc = t >> 12;
    int c = bc & 127, b = bc >> 7;
    float a  = g_bna[2*128 + c];
    float cc = g_bnc[2*128 + c];
    const float2* mm = (const float2*)(g_scr + OFF_MM);
    float2 e = mm[(size_t)c*NGRP + b*SS + s];
    float z = (a >= 0.f) ? e.x : e.y;
    out[BB*3*SS + t] = fmaxf(fmaf(a, z, cc), 0.f);
}

// ---------------- launch (single stream, round-10 structure) ----------------
extern "C" void kernel_launch(void* const* d_in, const int* in_sizes, int n_in,
                              void* d_out, int out_size) {
    (void)in_sizes; (void)n_in; (void)out_size;
    const float* xyz   = (const float*)d_in[0];
    const float* feats = (const float*)d_in[1];
    const int*   perm  = (const int*)d_in[2];
    const float* w0 = (const float*)d_in[3];
    const float* g0 = (const float*)d_in[4];
    const float* b0 = (const float*)d_in[5];
    const float* w1 = (const float*)d_in[6];
    const float* g1 = (const float*)d_in[7];
    const float* b1 = (const float*)d_in[8];
    const float* w2 = (const float*)d_in[9];
    const float* g2 = (const float*)d_in[10];
    const float* b2 = (const float*)d_in[11];
    float* out = (float*)d_out;

    const int sm0  = (512 + 64*XS + 64*128) * 4;   // 68608 (gemm0)
    const int smm1 = 54784;
    const int smm2 = 70144;
    cudaFuncSetAttribute(k_gemm0, cudaFuncAttributeMaxDynamicSharedMemorySize, sm0);
    cudaFuncSetAttribute(k_mma1,  cudaFuncAttributeMaxDynamicSharedMemorySize, smm1);
    cudaFuncSetAttribute(k_mma2,  cudaFuncAttributeMaxDynamicSharedMemorySize, smm2);

    k_prep0 <<<(BB*NN)/256, 256>>>(xyz, perm, out);
    k_prepw <<<64, 256>>>(w0, w1, w2);
    k_knn   <<<SS/8, 256>>>();
    k_gemm0 <<<BB*NN/128, 128, sm0>>>(feats);
    k_stats1<<<NCOL/1024, 256>>>(w0);
    k_bnparam<<<1,128>>>(0, g0, b0, 64);
    k_mma1  <<<NCOL/128, 128, smm1>>>(w0);
    k_bnparam<<<1,128>>>(1, g1, b1, 64);
    k_mma2  <<<NCOL/128, 256, smm2>>>();
    k_bnparam<<<1,128>>>(2, g2, b2, 128);
    k_final<<<(BB*128*SS)/256, 256>>>(out);
}